// round 10
// baseline (speedup 1.0000x reference)
#include <cuda_runtime.h>
#include <cuda_bf16.h>
#include <cuda_fp16.h>
#include <stdint.h>
#include <math.h>

// Problem constants: B=16, X=4, I=8 -> G=512 groups; Lc=256, Lq=128, H=512
#define NG 512
#define LCC 256
#define LQQ 128
#define HD 512
#define FSCALE 100.0f
#define LOG2E 1.4426950408889634f
#define FPEN2 1.4426950e12f            // NEG_BIG * SCALE * log2(e)

// Scratch (static device globals: allocation-free per harness rules)
// P matrices stored as fp16 (quantization 2^-11, enters outputs linearly).
__device__ __align__(16) __half g_PcH[NG * LCC * LQQ];  // row softmax * mask [c][q]
__device__ __align__(16) __half g_PqH[NG * LCC * LQQ];  // col softmax * mask [c][q]

// ---------------------------------------------------------------------------
// helpers
// ---------------------------------------------------------------------------
static __device__ __forceinline__ uint32_t smem_u32(const void* p) {
    uint32_t a;
    asm("{ .reg .u64 t; cvta.to.shared.u64 t, %1; cvt.u32.u64 %0, t; }"
        : "=r"(a) : "l"(p));
    return a;
}

// pack two floats as bf16x2 {lo, hi}
static __device__ __forceinline__ uint32_t pack_bf2(float lo, float hi) {
    uint32_t r;
    asm("cvt.rn.bf16x2.f32 %0, %1, %2;" : "=r"(r) : "f"(hi), "f"(lo));
    return r;
}

// split a float4 into bf16 hi/lo pairs and store 8B each to smem (fused_S)
static __device__ __forceinline__ void split_store(uint8_t* sh, uint8_t* sl,
                                                   int off, float4 v) {
    float hx = __bfloat162float(__float2bfloat16(v.x));
    float hy = __bfloat162float(__float2bfloat16(v.y));
    float hz = __bfloat162float(__float2bfloat16(v.z));
    float hw = __bfloat162float(__float2bfloat16(v.w));
    uint2 H, L;
    H.x = pack_bf2(hx, hy);
    H.y = pack_bf2(hz, hw);
    L.x = pack_bf2(v.x - hx, v.y - hy);
    L.y = pack_bf2(v.z - hz, v.w - hw);
    *(uint2*)(sh + off) = H;
    *(uint2*)(sl + off) = L;
}

// split a float4 into fp16 hi/lo pairs and store 8B each to smem (nn_gemm B)
static __device__ __forceinline__ void split_store_h(uint8_t* sh, uint8_t* sl,
                                                     int off, float4 v) {
    __half hx = __float2half_rn(v.x), hy = __float2half_rn(v.y);
    __half hz = __float2half_rn(v.z), hw = __float2half_rn(v.w);
    __half2 H0 = __halves2half2(hx, hy), H1 = __halves2half2(hz, hw);
    __half2 L0 = __floats2half2_rn(v.x - __half2float(hx), v.y - __half2float(hy));
    __half2 L1 = __floats2half2_rn(v.z - __half2float(hz), v.w - __half2float(hw));
    uint2 H, L;
    H.x = *(uint32_t*)&H0; H.y = *(uint32_t*)&H1;
    L.x = *(uint32_t*)&L0; L.y = *(uint32_t*)&L1;
    *(uint2*)(sh + off) = H;
    *(uint2*)(sl + off) = L;
}

static __device__ __forceinline__ void ldm4(uint32_t* r, uint32_t a) {
    asm volatile("ldmatrix.sync.aligned.m8n8.x4.shared.b16 {%0,%1,%2,%3}, [%4];"
                 : "=r"(r[0]), "=r"(r[1]), "=r"(r[2]), "=r"(r[3]) : "r"(a));
}
static __device__ __forceinline__ void ldm4t(uint32_t* r, uint32_t a) {
    asm volatile("ldmatrix.sync.aligned.m8n8.x4.trans.shared.b16 {%0,%1,%2,%3}, [%4];"
                 : "=r"(r[0]), "=r"(r[1]), "=r"(r[2]), "=r"(r[3]) : "r"(a));
}

static __device__ __forceinline__ void mma16816(float* d, const uint32_t* a,
                                                const uint32_t* b) {
    asm volatile(
        "mma.sync.aligned.m16n8k16.row.col.f32.bf16.bf16.f32 "
        "{%0,%1,%2,%3}, {%4,%5,%6,%7}, {%8,%9}, {%0,%1,%2,%3};"
        : "+f"(d[0]), "+f"(d[1]), "+f"(d[2]), "+f"(d[3])
        : "r"(a[0]), "r"(a[1]), "r"(a[2]), "r"(a[3]), "r"(b[0]), "r"(b[1]));
}
static __device__ __forceinline__ void mma16816h(float* d, const uint32_t* a,
                                                 const uint32_t* b) {
    asm volatile(
        "mma.sync.aligned.m16n8k16.row.col.f32.f16.f16.f32 "
        "{%0,%1,%2,%3}, {%4,%5,%6,%7}, {%8,%9}, {%0,%1,%2,%3};"
        : "+f"(d[0]), "+f"(d[1]), "+f"(d[2]), "+f"(d[3])
        : "r"(a[0]), "r"(a[1]), "r"(a[2]), "r"(a[3]), "r"(b[0]), "r"(b[1]));
}

// ---------------------------------------------------------------------------
// Fused: S logits in LOG2 domain (HMMA bf16 hi/lo) for the whole group
// (256x128) in smem, in-kernel L2 norms, dual softmax with cached exps:
//   e_c = exp2(v-colmax) -> EC (fp16, reuses A/B staging smem)
//   e_r = exp2(v-rowmax) -> overwrites S
//   write pass: NO exps, just scale+pack fp16.
// One CTA per group, 512 threads (16 warps, 4m x 4n).
// ---------------------------------------------------------------------------
#define OFF_S      0
#define SSTRIDE    132                       // floats; keeps float4 alignment
#define OFF_AH     (256 * SSTRIDE * 4)       // 135168
#define OFF_AL     (OFF_AH + 20480)
#define OFF_BH     (OFF_AL + 20480)
#define OFF_BL     (OFF_BH + 10240)          // ends 196608
#define OFF_EC     OFF_AH                    // 256*128 fp16 = 65536; ends 200704
#define OFF_IC     200704                    // 256 f
#define OFF_CM     (OFF_IC + 1024)           // 256 f
#define OFF_IQ     (OFF_CM + 1024)           // 128 f
#define OFF_QM     (OFF_IQ + 512)            // 128 f
#define OFF_RMAX   (OFF_QM + 512)            // 256 f
#define OFF_RINV   (OFF_RMAX + 1024)         // 256 f
#define OFF_CMAX   (OFF_RINV + 1024)         // 128 f
#define OFF_CINV   (OFF_CMAX + 512)          // 128 f
#define OFF_PM     (OFF_CINV + 512)          // 4*128 f
#define OFF_PS     (OFF_PM + 2048)           // 4*128 f
#define SMEM_FUSED (OFF_PS + 2048)           // 210944 bytes

__global__ __launch_bounds__(512, 1) void fused_S(
    const float* __restrict__ Cin, const float* __restrict__ Qin,
    const float* __restrict__ cm, const float* __restrict__ qm,
    float* __restrict__ outM, float* __restrict__ outMT) {
    extern __shared__ __align__(16) uint8_t dsm[];
    float* S      = (float*)(dsm + OFF_S);
    uint8_t* Ah   = dsm + OFF_AH;
    uint8_t* Al   = dsm + OFF_AL;
    uint8_t* Bh   = dsm + OFF_BH;
    uint8_t* Bl   = dsm + OFF_BL;
    __half* EC    = (__half*)(dsm + OFF_EC);
    float* s_ic   = (float*)(dsm + OFF_IC);
    float* s_cm   = (float*)(dsm + OFF_CM);
    float* s_iq   = (float*)(dsm + OFF_IQ);
    float* s_qm   = (float*)(dsm + OFF_QM);
    float* rowmax = (float*)(dsm + OFF_RMAX);
    float* rowinv = (float*)(dsm + OFF_RINV);
    float* colmax = (float*)(dsm + OFF_CMAX);
    float* colinv = (float*)(dsm + OFF_CINV);
    float* pm     = (float*)(dsm + OFF_PM);
    float* ps     = (float*)(dsm + OFF_PS);

    int t = threadIdx.x, lane = t & 31, wid = t >> 5;
    int wm = wid & 3, wn = wid >> 2;
    int g = blockIdx.x;
    if (t < 256) s_cm[t] = cm[g * LCC + t];
    else if (t < 384) s_qm[t - 256] = qm[g * LQQ + (t - 256)];
    const float* Ag = Cin + (size_t)g * LCC * HD;
    const float* Bg = Qin + (size_t)g * LQQ * HD;

    float4 pvA[4], pvB[2];
    float sqA[4] = {}, sqB[2] = {};
#pragma unroll
    for (int i = 0; i < 4; i++) {
        int idx = t + i * 512;
        pvA[i] = *(const float4*)(Ag + (size_t)(idx >> 3) * HD + (idx & 7) * 4);
    }
#pragma unroll
    for (int i = 0; i < 2; i++) {
        int idx = t + i * 512;
        pvB[i] = *(const float4*)(Bg + (size_t)(idx >> 3) * HD + (idx & 7) * 4);
    }
    __syncthreads();

    // ---- mask outputs (independent of GEMM; fills LDG latency) ----
    {
        float* oM = outM + (size_t)g * LCC * LQQ;
#pragma unroll
        for (int i = 0; i < 16; i++) {
            int base = (i * 512 + t) * 4;
            int r = base >> 7, c = base & 127;
            float cv = s_cm[r];
            float4 o = {cv * s_qm[c], cv * s_qm[c + 1], cv * s_qm[c + 2], cv * s_qm[c + 3]};
            *(float4*)(oM + base) = o;
        }
        float* oT = outMT + (size_t)g * LCC * LQQ;
#pragma unroll
        for (int i = 0; i < 16; i++) {
            int base = (i * 512 + t) * 4;
            int r = base >> 8, c = base & 255;
            float qv = s_qm[r];
            float4 o = {qv * s_cm[c], qv * s_cm[c + 1], qv * s_cm[c + 2], qv * s_cm[c + 3]};
            *(float4*)(oT + base) = o;
        }
    }

    // ---- K loop: 16 chunks of BK=32, register-prefetch pipelined ----
    float acc[4][4][4] = {};
    for (int kc = 0; kc < 16; kc++) {
#pragma unroll
        for (int i = 0; i < 4; i++) {
            int idx = t + i * 512;
            float4 v = pvA[i];
            sqA[i] = fmaf(v.x, v.x, fmaf(v.y, v.y, fmaf(v.z, v.z, fmaf(v.w, v.w, sqA[i]))));
            split_store(Ah, Al, (idx >> 3) * 80 + (idx & 7) * 8, v);
        }
#pragma unroll
        for (int i = 0; i < 2; i++) {
            int idx = t + i * 512;
            float4 v = pvB[i];
            sqB[i] = fmaf(v.x, v.x, fmaf(v.y, v.y, fmaf(v.z, v.z, fmaf(v.w, v.w, sqB[i]))));
            split_store(Bh, Bl, (idx >> 3) * 80 + (idx & 7) * 8, v);
        }
        __syncthreads();
        if (kc < 15) {
            int k0 = (kc + 1) * 32;
#pragma unroll
            for (int i = 0; i < 4; i++) {
                int idx = t + i * 512;
                pvA[i] = *(const float4*)(Ag + (size_t)(idx >> 3) * HD + k0 + (idx & 7) * 4);
            }
#pragma unroll
            for (int i = 0; i < 2; i++) {
                int idx = t + i * 512;
                pvB[i] = *(const float4*)(Bg + (size_t)(idx >> 3) * HD + k0 + (idx & 7) * 4);
            }
        }
#pragma unroll
        for (int k16 = 0; k16 < 2; k16++) {
            uint32_t af[4][4], bh[4][2], bl[4][2];
            int colb = k16 * 32 + ((lane >> 4) & 1) * 16;
            int ra = wm * 64 + (lane & 15);
            int rb = wn * 32 + (lane & 15);
#pragma unroll
            for (int bg2 = 0; bg2 < 2; bg2++) {
                uint32_t r4[4];
                ldm4(r4, smem_u32(Bh + (rb + bg2 * 16) * 80 + colb));
                bh[bg2 * 2][0] = r4[0]; bh[bg2 * 2][1] = r4[2];
                bh[bg2 * 2 + 1][0] = r4[1]; bh[bg2 * 2 + 1][1] = r4[3];
                ldm4(r4, smem_u32(Bl + (rb + bg2 * 16) * 80 + colb));
                bl[bg2 * 2][0] = r4[0]; bl[bg2 * 2][1] = r4[2];
                bl[bg2 * 2 + 1][0] = r4[1]; bl[bg2 * 2 + 1][1] = r4[3];
            }
#pragma unroll
            for (int fm = 0; fm < 4; fm++)
                ldm4(af[fm], smem_u32(Ah + (ra + fm * 16) * 80 + colb));
#pragma unroll
            for (int fm = 0; fm < 4; fm++)
#pragma unroll
                for (int ni = 0; ni < 4; ni++) {
                    mma16816(acc[fm][ni], af[fm], bh[ni]);
                    mma16816(acc[fm][ni], af[fm], bl[ni]);
                }
#pragma unroll
            for (int fm = 0; fm < 4; fm++)
                ldm4(af[fm], smem_u32(Al + (ra + fm * 16) * 80 + colb));
#pragma unroll
            for (int fm = 0; fm < 4; fm++)
#pragma unroll
                for (int ni = 0; ni < 4; ni++)
                    mma16816(acc[fm][ni], af[fm], bh[ni]);
        }
        __syncthreads();
    }

    // ---- in-kernel norms (log2 domain scale folded into s_ic) ----
#pragma unroll
    for (int i = 0; i < 4; i++) {
        float s = sqA[i];
        s += __shfl_xor_sync(0xffffffffu, s, 4);
        s += __shfl_xor_sync(0xffffffffu, s, 2);
        s += __shfl_xor_sync(0xffffffffu, s, 1);
        if ((t & 7) == 0)
            s_ic[(t >> 3) + 64 * i] = (FSCALE * LOG2E) / fmaxf(sqrtf(s), 1e-12f);
    }
#pragma unroll
    for (int i = 0; i < 2; i++) {
        float s = sqB[i];
        s += __shfl_xor_sync(0xffffffffu, s, 4);
        s += __shfl_xor_sync(0xffffffffu, s, 2);
        s += __shfl_xor_sync(0xffffffffu, s, 1);
        if ((t & 7) == 0) s_iq[(t >> 3) + 64 * i] = 1.f / fmaxf(sqrtf(s), 1e-12f);
    }
    __syncthreads();

    // ---- log2-domain logits -> S smem ----
    int g2 = lane >> 2, t4 = lane & 3;
#pragma unroll
    for (int fm = 0; fm < 4; fm++)
#pragma unroll
        for (int half = 0; half < 2; half++) {
            int row = wm * 64 + fm * 16 + g2 + half * 8;
            float ic = s_ic[row], cv = s_cm[row];
#pragma unroll
            for (int ni = 0; ni < 4; ni++) {
                int col = wn * 32 + ni * 8 + t4 * 2;
                S[row * SSTRIDE + col]     = acc[fm][ni][half * 2]     * ic * s_iq[col]     - FPEN2 * (1.f - cv * s_qm[col]);
                S[row * SSTRIDE + col + 1] = acc[fm][ni][half * 2 + 1] * ic * s_iq[col + 1] - FPEN2 * (1.f - cv * s_qm[col + 1]);
            }
        }
    __syncthreads();

    // ---- pass 1: row max (2 threads per row, rotated columns) ----
    {
        int r = t >> 1, h = (t & 1) * 64;
        const float* sr = S + r * SSTRIDE;
        float m = -3.0e38f;
#pragma unroll 8
        for (int cc = 0; cc < 64; cc++) m = fmaxf(m, sr[h + ((cc + t) & 63)]);
        m = fmaxf(m, __shfl_xor_sync(0xffffffffu, m, 1));
        if (!(t & 1)) rowmax[r] = m;
    }
    // ---- pass 2: col max partials ----
    {
        int c = t & 127, part = t >> 7;
        const float* sc = S + (part * 64) * SSTRIDE + c;
        float m = -3.0e38f;
#pragma unroll 8
        for (int r2 = 0; r2 < 64; r2++) m = fmaxf(m, sc[r2 * SSTRIDE]);
        pm[part * 128 + c] = m;
    }
    __syncthreads();
    if (t < 128)
        colmax[t] = fmaxf(fmaxf(pm[t], pm[128 + t]), fmaxf(pm[256 + t], pm[384 + t]));
    __syncthreads();

    // ---- pass 3: e_c = exp2(v - colmax) -> EC fp16, colsum partials ----
    {
        int c = t & 127, part = t >> 7;
        float cmx = colmax[c];
        const float* sc = S + (part * 64) * SSTRIDE + c;
        __half* ec = EC + part * 64 * 128 + c;
        float s = 0.f;
#pragma unroll 4
        for (int r2 = 0; r2 < 64; r2++) {
            float e = exp2f(sc[r2 * SSTRIDE] - cmx);
            s += e;
            ec[r2 * 128] = __float2half_rn(e);
        }
        ps[part * 128 + c] = s;
    }
    __syncthreads();

    // ---- pass 4: e_r = exp2(v - rowmax) overwrites S, rowsum ----
    {
        int r = t >> 1, h = (t & 1) * 64;
        float rm = rowmax[r];
        float* sr = S + r * SSTRIDE;
        float s = 0.f;
#pragma unroll 4
        for (int cc = 0; cc < 64; cc++) {
            int ci = h + ((cc + t) & 63);
            float e = exp2f(sr[ci] - rm);
            sr[ci] = e;
            s += e;
        }
        s += __shfl_xor_sync(0xffffffffu, s, 1);
        if (!(t & 1)) rowinv[r] = s_cm[r] / s;
    }
    if (t < 128)
        colinv[t] = s_qm[t] / (ps[t] + ps[128 + t] + ps[256 + t] + ps[384 + t]);
    __syncthreads();

    // ---- write pass: NO exps ----
    __half* Pc = g_PcH + (size_t)g * LCC * LQQ;
    __half* Pq = g_PqH + (size_t)g * LCC * LQQ;
#pragma unroll
    for (int i = 0; i < 16; i++) {
        int base = (i * 512 + t) * 4;
        int r = base >> 7, c = base & 127;
        float4 e = *(const float4*)(S + r * SSTRIDE + c);
        uint2 eu = *(const uint2*)(EC + r * 128 + c);
        __half2 eh0 = *(__half2*)&eu.x, eh1 = *(__half2*)&eu.y;
        float2 f0 = __half22float2(eh0), f1 = __half22float2(eh1);
        float ri = rowinv[r], cv = s_cm[r];
        __half2 c0 = __floats2half2_rn(e.x * ri * s_qm[c],     e.y * ri * s_qm[c + 1]);
        __half2 c1 = __floats2half2_rn(e.z * ri * s_qm[c + 2], e.w * ri * s_qm[c + 3]);
        __half2 q0 = __floats2half2_rn(f0.x * colinv[c]     * cv, f0.y * colinv[c + 1] * cv);
        __half2 q1 = __floats2half2_rn(f1.x * colinv[c + 2] * cv, f1.y * colinv[c + 3] * cv);
        uint2 uc, uq;
        uc.x = *(uint32_t*)&c0; uc.y = *(uint32_t*)&c1;
        uq.x = *(uint32_t*)&q0; uq.y = *(uint32_t*)&q1;
        *(uint2*)(Pc + base) = uc;
        *(uint2*)(Pq + base) = uq;
    }
}

// ---------------------------------------------------------------------------
// NN GEMM: out[M,512] = A[M,K] @ B[K,512] per group, fp16 2-MMA scheme.
// A = P (fp16, single plane).  B = Q/C (fp32 -> fp16 hi/lo split, 2 MMAs).
// ATRANS=false: A = g_PcH row-major [m][k];  Ac: M=256, K=128.
// ATRANS=true : A = g_PqH stored [k=c][m=q]; Aq: M=128, K=256 (A^T product).
// SMEM double buffer, one __syncthreads per k-chunk.
// ---------------------------------------------------------------------------
template<bool ATRANS>
__global__ __launch_bounds__(256) void nn_gemm(const float* __restrict__ Bg0,
                                               float* __restrict__ out,
                                               int M, int K) {
    constexpr int ASZ = ATRANS ? (32 * 272) : (128 * 80);  // one fp16 plane
    constexpr int SS  = ASZ + 2 * 8704;                    // A | Bh | Bl
    extern __shared__ __align__(16) uint8_t dsm2[];
    int t = threadIdx.x, lane = t & 31, wid = t >> 5;
    int wm = wid & 1, wn = wid >> 1;
    int g = blockIdx.z, m0 = blockIdx.y * 128, n0 = blockIdx.x * 128;
    const __half* AgH = (ATRANS ? g_PqH : g_PcH) + (size_t)g * LCC * LQQ;
    const float* Bg = Bg0 + (size_t)g * K * HD;
    float acc[4][4][4] = {};
    int KCH = K >> 5;

    uint4 pvA[2];
    float4 pvB[4];

#define LOADA(kc_) do {                                                        \
    if (!ATRANS) {                                                             \
        const __half* p = AgH + (size_t)(m0 + (t >> 1)) * K + (kc_) * 32 + (t & 1) * 16; \
        pvA[0] = *(const uint4*)p; pvA[1] = *(const uint4*)(p + 8);            \
    } else {                                                                   \
        const __half* p = AgH + (size_t)((kc_) * 32 + (t >> 3)) * M + (t & 7) * 16; \
        pvA[0] = *(const uint4*)p; pvA[1] = *(const uint4*)(p + 8);            \
    } } while (0)
#define STOREA(Ap_) do {                                                       \
    uint8_t* d_ = (Ap_) + (!ATRANS ? ((t >> 1) * 80 + (t & 1) * 32)            \
                                   : ((t >> 3) * 272 + (t & 7) * 32));         \
    *(uint4*)d_ = pvA[0]; *(uint4*)(d_ + 16) = pvA[1]; } while (0)
#define LOADB(kc_) do {                                                        \
    _Pragma("unroll") for (int i = 0; i < 4; i++) {                            \
        int idx = t + i * 256;                                                 \
        pvB[i] = *(const float4*)(Bg + (size_t)((kc_) * 32 + (idx >> 5)) * HD + n0 + (idx & 31) * 4); \
    } } while (0)
#define STOREB(Bh_, Bl_) do {                                                  \
    _Pragma("unroll") for (int i = 0; i < 4; i++) {                            \
        int idx = t + i * 256;                                                 \
        split_store_h((Bh_), (Bl_), (idx >> 5) * 272 + (idx & 31) * 8, pvB[i]);\
    } } while (0)

    LOADA(0); LOADB(0);
    {
        uint8_t* Ap = dsm2;
        STOREA(Ap); STOREB(Ap + ASZ, Ap + ASZ + 8704);
    }

    for (int kc = 0; kc < KCH; kc++) {
        __syncthreads();
        uint8_t* Ap = dsm2 + (kc & 1) * SS;
        uint8_t* Bh = Ap + ASZ;
        uint8_t* Bl = Bh + 8704;
        bool more = (kc + 1 < KCH);
        if (more) { LOADA(kc + 1); LOADB(kc + 1); }
#pragma unroll
        for (int k16 = 0; k16 < 2; k16++) {
            uint32_t af[4][4], bh[4][2], bl[4][2];
            if (!ATRANS) {
                int colb = k16 * 32 + ((lane >> 4) & 1) * 16;
                int ra = wm * 64 + (lane & 15);
#pragma unroll
                for (int fm = 0; fm < 4; fm++)
                    ldm4(af[fm], smem_u32(Ap + (ra + fm * 16) * 80 + colb));
            } else {
                int row = k16 * 16 + (lane & 7) + ((lane >> 4) & 1) * 8;
                int cb  = wm * 128 + ((lane >> 3) & 1) * 16;
#pragma unroll
                for (int fm = 0; fm < 4; fm++)
                    ldm4t(af[fm], smem_u32(Ap + row * 272 + cb + fm * 32));
            }
            {
                int rowb = k16 * 16 + (lane & 7) + ((lane >> 3) & 1) * 8;
                int cbb  = wn * 64 + ((lane >> 4) & 1) * 16;
#pragma unroll
                for (int bg = 0; bg < 2; bg++) {
                    uint32_t r4[4];
                    ldm4t(r4, smem_u32(Bh + rowb * 272 + cbb + bg * 32));
                    bh[bg * 2][0] = r4[0]; bh[bg * 2][1] = r4[1];
                    bh[bg * 2 + 1][0] = r4[2]; bh[bg * 2 + 1][1] = r4[3];
                    ldm4t(r4, smem_u32(Bl + rowb * 272 + cbb + bg * 32));
                    bl[bg * 2][0] = r4[0]; bl[bg * 2][1] = r4[1];
                    bl[bg * 2 + 1][0] = r4[2]; bl[bg * 2 + 1][1] = r4[3];
                }
            }
#pragma unroll
            for (int fm = 0; fm < 4; fm++)
#pragma unroll
                for (int ni = 0; ni < 4; ni++) {
                    mma16816h(acc[fm][ni], af[fm], bh[ni]);
                    mma16816h(acc[fm][ni], af[fm], bl[ni]);
                }
        }
        if (more) {
            uint8_t* nAp = dsm2 + ((kc + 1) & 1) * SS;
            STOREA(nAp); STOREB(nAp + ASZ, nAp + ASZ + 8704);
        }
    }
#undef LOADA
#undef STOREA
#undef LOADB
#undef STOREB

    int g2 = lane >> 2, t4 = lane & 3;
#pragma unroll
    for (int fm = 0; fm < 4; fm++)
#pragma unroll
        for (int half = 0; half < 2; half++) {
            int row = m0 + wm * 64 + fm * 16 + g2 + half * 8;
            float* dst = out + ((size_t)g * M + row) * HD + n0;
#pragma unroll
            for (int ni = 0; ni < 4; ni++) {
                int col = wn * 32 + ni * 8 + t4 * 2;
                float2 o = {acc[fm][ni][half * 2], acc[fm][ni][half * 2 + 1]};
                *(float2*)(dst + col) = o;
            }
        }
}

// ---------------------------------------------------------------------------
extern "C" void kernel_launch(void* const* d_in, const int* in_sizes, int n_in,
                              void* d_out, int out_size) {
    const float* Cin = (const float*)d_in[0];
    const float* Qin = (const float*)d_in[1];
    const float* cm  = (const float*)d_in[2];
    const float* qm  = (const float*)d_in[3];
    float* out   = (float*)d_out;
    float* outAc = out;
    float* outAq = outAc + (size_t)NG * LCC * HD;
    float* outM  = outAq + (size_t)NG * LQQ * HD;
    float* outMT = outM  + (size_t)NG * LCC * LQQ;

    constexpr int SS_F = 128 * 80 + 2 * 8704;   // 27648
    constexpr int SS_T = 32 * 272 + 2 * 8704;   // 26112

    cudaFuncSetAttribute(fused_S, cudaFuncAttributeMaxDynamicSharedMemorySize,
                         SMEM_FUSED);
    cudaFuncSetAttribute(nn_gemm<false>,
                         cudaFuncAttributeMaxDynamicSharedMemorySize, 2 * SS_F);
    cudaFuncSetAttribute(nn_gemm<true>,
                         cudaFuncAttributeMaxDynamicSharedMemorySize, 2 * SS_T);

    fused_S<<<NG, 512, SMEM_FUSED>>>(Cin, Qin, cm, qm, outM, outMT);
    nn_gemm<false><<<dim3(4, 2, NG), 256, 2 * SS_F>>>(Qin, outAc, LCC, LQQ);
    nn_gemm<true ><<<dim3(4, 1, NG), 256, 2 * SS_T>>>(Cin, outAq, LQQ, LCC);
}

// round 11
// speedup vs baseline: 1.1744x; 1.1744x over previous
#include <cuda_runtime.h>
#include <cuda_bf16.h>
#include <cuda_fp16.h>
#include <stdint.h>
#include <math.h>

// Problem constants: B=16, X=4, I=8 -> G=512 groups; Lc=256, Lq=128, H=512
#define NG 512
#define LCC 256
#define LQQ 128
#define HD 512
#define FSCALE 100.0f
#define LOG2E 1.4426950408889634f
#define FPEN2 1.4426950e12f            // NEG_BIG * SCALE * log2(e)

// Scratch (static device globals: allocation-free per harness rules)
__device__ __align__(16) __half g_PcH[NG * LCC * LQQ];  // row softmax * mask [c][q]
__device__ __align__(16) __half g_PqH[NG * LCC * LQQ];  // col softmax * mask [c][q]

// ---------------------------------------------------------------------------
// helpers
// ---------------------------------------------------------------------------
static __device__ __forceinline__ uint32_t smem_u32(const void* p) {
    uint32_t a;
    asm("{ .reg .u64 t; cvta.to.shared.u64 t, %1; cvt.u32.u64 %0, t; }"
        : "=r"(a) : "l"(p));
    return a;
}

static __device__ __forceinline__ uint32_t pack_bf2(float lo, float hi) {
    uint32_t r;
    asm("cvt.rn.bf16x2.f32 %0, %1, %2;" : "=r"(r) : "f"(hi), "f"(lo));
    return r;
}

// split a float4 into bf16 hi/lo pairs and store 8B each to smem (fused_S)
static __device__ __forceinline__ void split_store(uint8_t* sh, uint8_t* sl,
                                                   int off, float4 v) {
    float hx = __bfloat162float(__float2bfloat16(v.x));
    float hy = __bfloat162float(__float2bfloat16(v.y));
    float hz = __bfloat162float(__float2bfloat16(v.z));
    float hw = __bfloat162float(__float2bfloat16(v.w));
    uint2 H, L;
    H.x = pack_bf2(hx, hy);
    H.y = pack_bf2(hz, hw);
    L.x = pack_bf2(v.x - hx, v.y - hy);
    L.y = pack_bf2(v.z - hz, v.w - hw);
    *(uint2*)(sh + off) = H;
    *(uint2*)(sl + off) = L;
}

// split a float4 into fp16 hi/lo pairs and store 8B each to smem (nn_gemm B)
static __device__ __forceinline__ void split_store_h(uint8_t* sh, uint8_t* sl,
                                                     int off, float4 v) {
    __half hx = __float2half_rn(v.x), hy = __float2half_rn(v.y);
    __half hz = __float2half_rn(v.z), hw = __float2half_rn(v.w);
    __half2 H0 = __halves2half2(hx, hy), H1 = __halves2half2(hz, hw);
    __half2 L0 = __floats2half2_rn(v.x - __half2float(hx), v.y - __half2float(hy));
    __half2 L1 = __floats2half2_rn(v.z - __half2float(hz), v.w - __half2float(hw));
    uint2 H, L;
    H.x = *(uint32_t*)&H0; H.y = *(uint32_t*)&H1;
    L.x = *(uint32_t*)&L0; L.y = *(uint32_t*)&L1;
    *(uint2*)(sh + off) = H;
    *(uint2*)(sl + off) = L;
}

static __device__ __forceinline__ void ldm4(uint32_t* r, uint32_t a) {
    asm volatile("ldmatrix.sync.aligned.m8n8.x4.shared.b16 {%0,%1,%2,%3}, [%4];"
                 : "=r"(r[0]), "=r"(r[1]), "=r"(r[2]), "=r"(r[3]) : "r"(a));
}
static __device__ __forceinline__ void ldm4t(uint32_t* r, uint32_t a) {
    asm volatile("ldmatrix.sync.aligned.m8n8.x4.trans.shared.b16 {%0,%1,%2,%3}, [%4];"
                 : "=r"(r[0]), "=r"(r[1]), "=r"(r[2]), "=r"(r[3]) : "r"(a));
}

static __device__ __forceinline__ void mma16816(float* d, const uint32_t* a,
                                                const uint32_t* b) {
    asm volatile(
        "mma.sync.aligned.m16n8k16.row.col.f32.bf16.bf16.f32 "
        "{%0,%1,%2,%3}, {%4,%5,%6,%7}, {%8,%9}, {%0,%1,%2,%3};"
        : "+f"(d[0]), "+f"(d[1]), "+f"(d[2]), "+f"(d[3])
        : "r"(a[0]), "r"(a[1]), "r"(a[2]), "r"(a[3]), "r"(b[0]), "r"(b[1]));
}
static __device__ __forceinline__ void mma16816h(float* d, const uint32_t* a,
                                                 const uint32_t* b) {
    asm volatile(
        "mma.sync.aligned.m16n8k16.row.col.f32.f16.f16.f32 "
        "{%0,%1,%2,%3}, {%4,%5,%6,%7}, {%8,%9}, {%0,%1,%2,%3};"
        : "+f"(d[0]), "+f"(d[1]), "+f"(d[2]), "+f"(d[3])
        : "r"(a[0]), "r"(a[1]), "r"(a[2]), "r"(a[3]), "r"(b[0]), "r"(b[1]));
}

// ---------------------------------------------------------------------------
// Fused: S logits (log2 domain) via HMMA bf16 hi/lo, kept ENTIRELY in the
// accumulator registers. Dual softmax via shfl + tiny smem partials.
// P_q / P_c leave through a padded fp16 smem buffer (EC, reuses dead staging)
// so all global P writes are 16B coalesced. One CTA/group, 512 thr, 16 warps.
// ---------------------------------------------------------------------------
#define OFF_AH     0
#define OFF_AL     20480
#define OFF_BH     40960
#define OFF_BL     51200                    // staging ends 61440
#define ECSTRIDE   272                      // bytes per 128-col fp16 row
#define OFF_EC     0                        // reuses staging after k-loop
#define OFF_CMS    69632                    // 256 f  (EC = 256*272 = 69632)
#define OFF_QMS    (OFF_CMS + 1024)         // 128 f
#define OFF_IC     (OFF_QMS + 512)          // 256 f
#define OFF_IQ     (OFF_IC + 1024)          // 128 f
#define OFF_RMAX   (OFF_IQ + 512)           // 256 f
#define OFF_RINV   (OFF_RMAX + 1024)        // 256 f
#define OFF_CMAX   (OFF_RINV + 1024)        // 128 f
#define OFF_CINV   (OFF_CMAX + 512)         // 128 f
#define OFF_RPART  (OFF_CINV + 512)         // 4*256 f
#define OFF_CPART  (OFF_RPART + 4096)       // 4*128 f
#define SMEM_FUSED (OFF_CPART + 2048)       // 81920 bytes

__global__ __launch_bounds__(512, 1) void fused_S(
    const float* __restrict__ Cin, const float* __restrict__ Qin,
    const float* __restrict__ cm, const float* __restrict__ qm,
    float* __restrict__ outM, float* __restrict__ outMT) {
    extern __shared__ __align__(16) uint8_t dsm[];
    uint8_t* Ah   = dsm + OFF_AH;
    uint8_t* Al   = dsm + OFF_AL;
    uint8_t* Bh   = dsm + OFF_BH;
    uint8_t* Bl   = dsm + OFF_BL;
    uint8_t* ecb  = dsm + OFF_EC;
    float* s_cm   = (float*)(dsm + OFF_CMS);
    float* s_qm   = (float*)(dsm + OFF_QMS);
    float* s_ic   = (float*)(dsm + OFF_IC);
    float* s_iq   = (float*)(dsm + OFF_IQ);
    float* rowmax = (float*)(dsm + OFF_RMAX);
    float* rowinv = (float*)(dsm + OFF_RINV);
    float* colmax = (float*)(dsm + OFF_CMAX);
    float* colinv = (float*)(dsm + OFF_CINV);
    float* rpart  = (float*)(dsm + OFF_RPART);
    float* cpart  = (float*)(dsm + OFF_CPART);

    int t = threadIdx.x, lane = t & 31, wid = t >> 5;
    int wm = wid & 3, wn = wid >> 2;
    int g2 = lane >> 2, t4 = lane & 3;
    int g = blockIdx.x;
    if (t < 256) s_cm[t] = cm[g * LCC + t];
    else if (t < 384) s_qm[t - 256] = qm[g * LQQ + (t - 256)];
    const float* Ag = Cin + (size_t)g * LCC * HD;
    const float* Bg = Qin + (size_t)g * LQQ * HD;

    float4 pvA[4], pvB[2];
    float sqA[4] = {}, sqB[2] = {};
#pragma unroll
    for (int i = 0; i < 4; i++) {
        int idx = t + i * 512;
        pvA[i] = *(const float4*)(Ag + (size_t)(idx >> 3) * HD + (idx & 7) * 4);
    }
#pragma unroll
    for (int i = 0; i < 2; i++) {
        int idx = t + i * 512;
        pvB[i] = *(const float4*)(Bg + (size_t)(idx >> 3) * HD + (idx & 7) * 4);
    }
    __syncthreads();

    // ---- mask outputs (independent; fills LDG latency) ----
    {
        float* oM = outM + (size_t)g * LCC * LQQ;
#pragma unroll
        for (int i = 0; i < 16; i++) {
            int base = (i * 512 + t) * 4;
            int r = base >> 7, c = base & 127;
            float cv = s_cm[r];
            float4 o = {cv * s_qm[c], cv * s_qm[c + 1], cv * s_qm[c + 2], cv * s_qm[c + 3]};
            *(float4*)(oM + base) = o;
        }
        float* oT = outMT + (size_t)g * LCC * LQQ;
#pragma unroll
        for (int i = 0; i < 16; i++) {
            int base = (i * 512 + t) * 4;
            int r = base >> 8, c = base & 255;
            float qv = s_qm[r];
            float4 o = {qv * s_cm[c], qv * s_cm[c + 1], qv * s_cm[c + 2], qv * s_cm[c + 3]};
            *(float4*)(oT + base) = o;
        }
    }

    // ---- K loop: 16 chunks of BK=32, register-prefetch pipelined ----
    float acc[4][4][4] = {};
    for (int kc = 0; kc < 16; kc++) {
#pragma unroll
        for (int i = 0; i < 4; i++) {
            int idx = t + i * 512;
            float4 v = pvA[i];
            sqA[i] = fmaf(v.x, v.x, fmaf(v.y, v.y, fmaf(v.z, v.z, fmaf(v.w, v.w, sqA[i]))));
            split_store(Ah, Al, (idx >> 3) * 80 + (idx & 7) * 8, v);
        }
#pragma unroll
        for (int i = 0; i < 2; i++) {
            int idx = t + i * 512;
            float4 v = pvB[i];
            sqB[i] = fmaf(v.x, v.x, fmaf(v.y, v.y, fmaf(v.z, v.z, fmaf(v.w, v.w, sqB[i]))));
            split_store(Bh, Bl, (idx >> 3) * 80 + (idx & 7) * 8, v);
        }
        __syncthreads();
        if (kc < 15) {
            int k0 = (kc + 1) * 32;
#pragma unroll
            for (int i = 0; i < 4; i++) {
                int idx = t + i * 512;
                pvA[i] = *(const float4*)(Ag + (size_t)(idx >> 3) * HD + k0 + (idx & 7) * 4);
            }
#pragma unroll
            for (int i = 0; i < 2; i++) {
                int idx = t + i * 512;
                pvB[i] = *(const float4*)(Bg + (size_t)(idx >> 3) * HD + k0 + (idx & 7) * 4);
            }
        }
#pragma unroll
        for (int k16 = 0; k16 < 2; k16++) {
            uint32_t af[4][4], bh[4][2], bl[4][2];
            int colb = k16 * 32 + ((lane >> 4) & 1) * 16;
            int ra = wm * 64 + (lane & 15);
            int rb = wn * 32 + (lane & 15);
#pragma unroll
            for (int bg2 = 0; bg2 < 2; bg2++) {
                uint32_t r4[4];
                ldm4(r4, smem_u32(Bh + (rb + bg2 * 16) * 80 + colb));
                bh[bg2 * 2][0] = r4[0]; bh[bg2 * 2][1] = r4[2];
                bh[bg2 * 2 + 1][0] = r4[1]; bh[bg2 * 2 + 1][1] = r4[3];
                ldm4(r4, smem_u32(Bl + (rb + bg2 * 16) * 80 + colb));
                bl[bg2 * 2][0] = r4[0]; bl[bg2 * 2][1] = r4[2];
                bl[bg2 * 2 + 1][0] = r4[1]; bl[bg2 * 2 + 1][1] = r4[3];
            }
#pragma unroll
            for (int fm = 0; fm < 4; fm++)
                ldm4(af[fm], smem_u32(Ah + (ra + fm * 16) * 80 + colb));
#pragma unroll
            for (int fm = 0; fm < 4; fm++)
#pragma unroll
                for (int ni = 0; ni < 4; ni++) {
                    mma16816(acc[fm][ni], af[fm], bh[ni]);
                    mma16816(acc[fm][ni], af[fm], bl[ni]);
                }
#pragma unroll
            for (int fm = 0; fm < 4; fm++)
                ldm4(af[fm], smem_u32(Al + (ra + fm * 16) * 80 + colb));
#pragma unroll
            for (int fm = 0; fm < 4; fm++)
#pragma unroll
                for (int ni = 0; ni < 4; ni++)
                    mma16816(acc[fm][ni], af[fm], bh[ni]);
        }
        __syncthreads();
    }

    // ---- in-kernel norms (log2-domain scale folded into s_ic) ----
#pragma unroll
    for (int i = 0; i < 4; i++) {
        float s = sqA[i];
        s += __shfl_xor_sync(0xffffffffu, s, 4);
        s += __shfl_xor_sync(0xffffffffu, s, 2);
        s += __shfl_xor_sync(0xffffffffu, s, 1);
        if ((t & 7) == 0)
            s_ic[(t >> 3) + 64 * i] = (FSCALE * LOG2E) / fmaxf(sqrtf(s), 1e-12f);
    }
#pragma unroll
    for (int i = 0; i < 2; i++) {
        float s = sqB[i];
        s += __shfl_xor_sync(0xffffffffu, s, 4);
        s += __shfl_xor_sync(0xffffffffu, s, 2);
        s += __shfl_xor_sync(0xffffffffu, s, 1);
        if ((t & 7) == 0) s_iq[(t >> 3) + 64 * i] = 1.f / fmaxf(sqrtf(s), 1e-12f);
    }
    __syncthreads();

    // ---- logits in registers (log2 domain) ----
    float iq8[8], qm8[8];
#pragma unroll
    for (int ni = 0; ni < 4; ni++)
#pragma unroll
        for (int b = 0; b < 2; b++) {
            int c = wn * 32 + ni * 8 + t4 * 2 + b;
            iq8[ni * 2 + b] = s_iq[c];
            qm8[ni * 2 + b] = s_qm[c];
        }
    float ic2[4][2], cv2[4][2];
#pragma unroll
    for (int fm = 0; fm < 4; fm++)
#pragma unroll
        for (int half = 0; half < 2; half++) {
            int r = wm * 64 + fm * 16 + g2 + half * 8;
            ic2[fm][half] = s_ic[r];
            cv2[fm][half] = s_cm[r];
        }
#pragma unroll
    for (int fm = 0; fm < 4; fm++)
#pragma unroll
        for (int ni = 0; ni < 4; ni++)
#pragma unroll
            for (int k = 0; k < 4; k++) {
                int half = k >> 1, b = k & 1;
                acc[fm][ni][k] = acc[fm][ni][k] * ic2[fm][half] * iq8[ni * 2 + b]
                               - FPEN2 * (1.f - cv2[fm][half] * qm8[ni * 2 + b]);
            }

    // ---- pass 1: maxes via shfl + 4-way partials ----
#pragma unroll
    for (int fm = 0; fm < 4; fm++)
#pragma unroll
        for (int half = 0; half < 2; half++) {
            float m = -3.0e38f;
#pragma unroll
            for (int ni = 0; ni < 4; ni++) {
                m = fmaxf(m, acc[fm][ni][half * 2]);
                m = fmaxf(m, acc[fm][ni][half * 2 + 1]);
            }
            m = fmaxf(m, __shfl_xor_sync(0xffffffffu, m, 1));
            m = fmaxf(m, __shfl_xor_sync(0xffffffffu, m, 2));
            if (t4 == 0)
                rpart[wn * 256 + wm * 64 + fm * 16 + g2 + half * 8] = m;
        }
#pragma unroll
    for (int ni = 0; ni < 4; ni++)
#pragma unroll
        for (int b = 0; b < 2; b++) {
            float m = -3.0e38f;
#pragma unroll
            for (int fm = 0; fm < 4; fm++) {
                m = fmaxf(m, acc[fm][ni][b]);
                m = fmaxf(m, acc[fm][ni][2 + b]);
            }
            m = fmaxf(m, __shfl_xor_sync(0xffffffffu, m, 4));
            m = fmaxf(m, __shfl_xor_sync(0xffffffffu, m, 8));
            m = fmaxf(m, __shfl_xor_sync(0xffffffffu, m, 16));
            if (g2 == 0)
                cpart[wm * 128 + wn * 32 + ni * 8 + t4 * 2 + b] = m;
        }
    __syncthreads();
    if (t < 256)
        rowmax[t] = fmaxf(fmaxf(rpart[t], rpart[256 + t]),
                          fmaxf(rpart[512 + t], rpart[768 + t]));
    else if (t < 384) {
        int c = t - 256;
        colmax[c] = fmaxf(fmaxf(cpart[c], cpart[128 + c]),
                          fmaxf(cpart[256 + c], cpart[384 + c]));
    }
    __syncthreads();

    // ---- pass 2: exps (e_r -> acc, e_c -> EC fp16), both sums ----
    float rm2[4][2], cmx[8];
#pragma unroll
    for (int fm = 0; fm < 4; fm++)
#pragma unroll
        for (int half = 0; half < 2; half++)
            rm2[fm][half] = rowmax[wm * 64 + fm * 16 + g2 + half * 8];
#pragma unroll
    for (int j = 0; j < 8; j++)
        cmx[j] = colmax[wn * 32 + (j >> 1) * 8 + t4 * 2 + (j & 1)];
    float rs[4][2] = {}, cs[8] = {};
#pragma unroll
    for (int fm = 0; fm < 4; fm++)
#pragma unroll
        for (int half = 0; half < 2; half++) {
            int r = wm * 64 + fm * 16 + g2 + half * 8;
#pragma unroll
            for (int ni = 0; ni < 4; ni++) {
                float v0 = acc[fm][ni][half * 2], v1 = acc[fm][ni][half * 2 + 1];
                float er0 = exp2f(v0 - rm2[fm][half]);
                float er1 = exp2f(v1 - rm2[fm][half]);
                float ec0 = exp2f(v0 - cmx[ni * 2]);
                float ec1 = exp2f(v1 - cmx[ni * 2 + 1]);
                rs[fm][half] += er0 + er1;
                cs[ni * 2] += ec0;
                cs[ni * 2 + 1] += ec1;
                acc[fm][ni][half * 2] = er0;
                acc[fm][ni][half * 2 + 1] = er1;
                __half2 h = __floats2half2_rn(ec0, ec1);
                int c = wn * 32 + ni * 8 + t4 * 2;
                *(uint32_t*)(ecb + r * ECSTRIDE + c * 2) = *(uint32_t*)&h;
            }
        }
    // reduce sums
#pragma unroll
    for (int fm = 0; fm < 4; fm++)
#pragma unroll
        for (int half = 0; half < 2; half++) {
            float s = rs[fm][half];
            s += __shfl_xor_sync(0xffffffffu, s, 1);
            s += __shfl_xor_sync(0xffffffffu, s, 2);
            if (t4 == 0)
                rpart[wn * 256 + wm * 64 + fm * 16 + g2 + half * 8] = s;
        }
#pragma unroll
    for (int j = 0; j < 8; j++) {
        float s = cs[j];
        s += __shfl_xor_sync(0xffffffffu, s, 4);
        s += __shfl_xor_sync(0xffffffffu, s, 8);
        s += __shfl_xor_sync(0xffffffffu, s, 16);
        if (g2 == 0)
            cpart[wm * 128 + wn * 32 + (j >> 1) * 8 + t4 * 2 + (j & 1)] = s;
    }
    __syncthreads();
    if (t < 256)
        rowinv[t] = s_cm[t] / (rpart[t] + rpart[256 + t] + rpart[512 + t] + rpart[768 + t]);
    else if (t < 384) {
        int c = t - 256;
        colinv[c] = s_qm[c] / (cpart[c] + cpart[128 + c] + cpart[256 + c] + cpart[384 + c]);
    }
    __syncthreads();

    // ---- P_q: scale EC by colinv*cm, coalesced 16B writes ----
    __half* Pq = g_PqH + (size_t)g * LCC * LQQ;
    __half* Pc = g_PcH + (size_t)g * LCC * LQQ;
#pragma unroll
    for (int i = 0; i < 8; i++) {
        int linear = i * 512 + t;
        int r = linear >> 4, c8 = (linear & 15) * 8;
        uint4 u = *(uint4*)(ecb + r * ECSTRIDE + c8 * 2);
        float cv = s_cm[r];
        __half2* hp = (__half2*)&u;
        uint4 o;
        __half2* op = (__half2*)&o;
#pragma unroll
        for (int j = 0; j < 4; j++) {
            float2 f = __half22float2(hp[j]);
            f.x *= colinv[c8 + j * 2] * cv;
            f.y *= colinv[c8 + j * 2 + 1] * cv;
            op[j] = __floats2half2_rn(f.x, f.y);
        }
        *(uint4*)(Pq + (size_t)r * LQQ + c8) = o;
    }
    __syncthreads();

    // ---- P_c: scale e_r in registers -> EC, then coalesced copy out ----
    float ri2[4][2];
#pragma unroll
    for (int fm = 0; fm < 4; fm++)
#pragma unroll
        for (int half = 0; half < 2; half++)
            ri2[fm][half] = rowinv[wm * 64 + fm * 16 + g2 + half * 8];
#pragma unroll
    for (int fm = 0; fm < 4; fm++)
#pragma unroll
        for (int half = 0; half < 2; half++) {
            int r = wm * 64 + fm * 16 + g2 + half * 8;
            float ri = ri2[fm][half];
#pragma unroll
            for (int ni = 0; ni < 4; ni++) {
                int c = wn * 32 + ni * 8 + t4 * 2;
                __half2 h = __floats2half2_rn(
                    acc[fm][ni][half * 2]     * ri * qm8[ni * 2],
                    acc[fm][ni][half * 2 + 1] * ri * qm8[ni * 2 + 1]);
                *(uint32_t*)(ecb + r * ECSTRIDE + c * 2) = *(uint32_t*)&h;
            }
        }
    __syncthreads();
#pragma unroll
    for (int i = 0; i < 8; i++) {
        int linear = i * 512 + t;
        int r = linear >> 4, c8 = (linear & 15) * 8;
        uint4 u = *(uint4*)(ecb + r * ECSTRIDE + c8 * 2);
        *(uint4*)(Pc + (size_t)r * LQQ + c8) = u;
    }
}

// ---------------------------------------------------------------------------
// NN GEMM: out[M,512] = A[M,K] @ B[K,512] per group, fp16 2-MMA scheme.
// A = P (fp16, single plane).  B = Q/C (fp32 -> fp16 hi/lo split, 2 MMAs).
// SMEM double buffer, one __syncthreads per k-chunk. (unchanged from R9)
// ---------------------------------------------------------------------------
template<bool ATRANS>
__global__ __launch_bounds__(256) void nn_gemm(const float* __restrict__ Bg0,
                                               float* __restrict__ out,
                                               int M, int K) {
    constexpr int ASZ = ATRANS ? (32 * 272) : (128 * 80);  // one fp16 plane
    constexpr int SS  = ASZ + 2 * 8704;                    // A | Bh | Bl
    extern __shared__ __align__(16) uint8_t dsm2[];
    int t = threadIdx.x, lane = t & 31, wid = t >> 5;
    int wm = wid & 1, wn = wid >> 1;
    int g = blockIdx.z, m0 = blockIdx.y * 128, n0 = blockIdx.x * 128;
    const __half* AgH = (ATRANS ? g_PqH : g_PcH) + (size_t)g * LCC * LQQ;
    const float* Bg = Bg0 + (size_t)g * K * HD;
    float acc[4][4][4] = {};
    int KCH = K >> 5;

    uint4 pvA[2];
    float4 pvB[4];

#define LOADA(kc_) do {                                                        \
    if (!ATRANS) {                                                             \
        const __half* p = AgH + (size_t)(m0 + (t >> 1)) * K + (kc_) * 32 + (t & 1) * 16; \
        pvA[0] = *(const uint4*)p; pvA[1] = *(const uint4*)(p + 8);            \
    } else {                                                                   \
        const __half* p = AgH + (size_t)((kc_) * 32 + (t >> 3)) * M + (t & 7) * 16; \
        pvA[0] = *(const uint4*)p; pvA[1] = *(const uint4*)(p + 8);            \
    } } while (0)
#define STOREA(Ap_) do {                                                       \
    uint8_t* d_ = (Ap_) + (!ATRANS ? ((t >> 1) * 80 + (t & 1) * 32)            \
                                   : ((t >> 3) * 272 + (t & 7) * 32));         \
    *(uint4*)d_ = pvA[0]; *(uint4*)(d_ + 16) = pvA[1]; } while (0)
#define LOADB(kc_) do {                                                        \
    _Pragma("unroll") for (int i = 0; i < 4; i++) {                            \
        int idx = t + i * 256;                                                 \
        pvB[i] = *(const float4*)(Bg + (size_t)((kc_) * 32 + (idx >> 5)) * HD + n0 + (idx & 31) * 4); \
    } } while (0)
#define STOREB(Bh_, Bl_) do {                                                  \
    _Pragma("unroll") for (int i = 0; i < 4; i++) {                            \
        int idx = t + i * 256;                                                 \
        split_store_h((Bh_), (Bl_), (idx >> 5) * 272 + (idx & 31) * 8, pvB[i]);\
    } } while (0)

    LOADA(0); LOADB(0);
    {
        uint8_t* Ap = dsm2;
        STOREA(Ap); STOREB(Ap + ASZ, Ap + ASZ + 8704);
    }

    for (int kc = 0; kc < KCH; kc++) {
        __syncthreads();
        uint8_t* Ap = dsm2 + (kc & 1) * SS;
        uint8_t* Bh = Ap + ASZ;
        uint8_t* Bl = Bh + 8704;
        bool more = (kc + 1 < KCH);
        if (more) { LOADA(kc + 1); LOADB(kc + 1); }
#pragma unroll
        for (int k16 = 0; k16 < 2; k16++) {
            uint32_t af[4][4], bh[4][2], bl[4][2];
            if (!ATRANS) {
                int colb = k16 * 32 + ((lane >> 4) & 1) * 16;
                int ra = wm * 64 + (lane & 15);
#pragma unroll
                for (int fm = 0; fm < 4; fm++)
                    ldm4(af[fm], smem_u32(Ap + (ra + fm * 16) * 80 + colb));
            } else {
                int row = k16 * 16 + (lane & 7) + ((lane >> 4) & 1) * 8;
                int cb  = wm * 128 + ((lane >> 3) & 1) * 16;
#pragma unroll
                for (int fm = 0; fm < 4; fm++)
                    ldm4t(af[fm], smem_u32(Ap + row * 272 + cb + fm * 32));
            }
            {
                int rowb = k16 * 16 + (lane & 7) + ((lane >> 3) & 1) * 8;
                int cbb  = wn * 64 + ((lane >> 4) & 1) * 16;
#pragma unroll
                for (int bg = 0; bg < 2; bg++) {
                    uint32_t r4[4];
                    ldm4t(r4, smem_u32(Bh + rowb * 272 + cbb + bg * 32));
                    bh[bg * 2][0] = r4[0]; bh[bg * 2][1] = r4[1];
                    bh[bg * 2 + 1][0] = r4[2]; bh[bg * 2 + 1][1] = r4[3];
                    ldm4t(r4, smem_u32(Bl + rowb * 272 + cbb + bg * 32));
                    bl[bg * 2][0] = r4[0]; bl[bg * 2][1] = r4[1];
                    bl[bg * 2 + 1][0] = r4[2]; bl[bg * 2 + 1][1] = r4[3];
                }
            }
#pragma unroll
            for (int fm = 0; fm < 4; fm++)
#pragma unroll
                for (int ni = 0; ni < 4; ni++) {
                    mma16816h(acc[fm][ni], af[fm], bh[ni]);
                    mma16816h(acc[fm][ni], af[fm], bl[ni]);
                }
        }
        if (more) {
            uint8_t* nAp = dsm2 + ((kc + 1) & 1) * SS;
            STOREA(nAp); STOREB(nAp + ASZ, nAp + ASZ + 8704);
        }
    }
#undef LOADA
#undef STOREA
#undef LOADB
#undef STOREB

    int g2 = lane >> 2, t4 = lane & 3;
#pragma unroll
    for (int fm = 0; fm < 4; fm++)
#pragma unroll
        for (int half = 0; half < 2; half++) {
            int row = m0 + wm * 64 + fm * 16 + g2 + half * 8;
            float* dst = out + ((size_t)g * M + row) * HD + n0;
#pragma unroll
            for (int ni = 0; ni < 4; ni++) {
                int col = wn * 32 + ni * 8 + t4 * 2;
                float2 o = {acc[fm][ni][half * 2], acc[fm][ni][half * 2 + 1]};
                *(float2*)(dst + col) = o;
            }
        }
}

// ---------------------------------------------------------------------------
extern "C" void kernel_launch(void* const* d_in, const int* in_sizes, int n_in,
                              void* d_out, int out_size) {
    const float* Cin = (const float*)d_in[0];
    const float* Qin = (const float*)d_in[1];
    const float* cm  = (const float*)d_in[2];
    const float* qm  = (const float*)d_in[3];
    float* out   = (float*)d_out;
    float* outAc = out;
    float* outAq = outAc + (size_t)NG * LCC * HD;
    float* outM  = outAq + (size_t)NG * LQQ * HD;
    float* outMT = outM  + (size_t)NG * LCC * LQQ;

    constexpr int SS_F = 128 * 80 + 2 * 8704;   // 27648
    constexpr int SS_T = 32 * 272 + 2 * 8704;   // 26112

    cudaFuncSetAttribute(fused_S, cudaFuncAttributeMaxDynamicSharedMemorySize,
                         SMEM_FUSED);
    cudaFuncSetAttribute(nn_gemm<false>,
                         cudaFuncAttributeMaxDynamicSharedMemorySize, 2 * SS_F);
    cudaFuncSetAttribute(nn_gemm<true>,
                         cudaFuncAttributeMaxDynamicSharedMemorySize, 2 * SS_T);

    fused_S<<<NG, 512, SMEM_FUSED>>>(Cin, Qin, cm, qm, outM, outMT);
    nn_gemm<false><<<dim3(4, 2, NG), 256, 2 * SS_F>>>(Qin, outAc, LCC, LQQ);
    nn_gemm<true ><<<dim3(4, 1, NG), 256, 2 * SS_T>>>(Cin, outAq, LQQ, LCC);
}

// round 12
// speedup vs baseline: 1.1746x; 1.0002x over previous
#include <cuda_runtime.h>
#include <cuda_bf16.h>
#include <cuda_fp16.h>
#include <stdint.h>
#include <math.h>

// Problem constants: B=16, X=4, I=8 -> G=512 groups; Lc=256, Lq=128, H=512
#define NG 512
#define LCC 256
#define LQQ 128
#define HD 512
#define FSCALE 100.0f
#define LOG2E 1.4426950408889634f
#define FPEN2 1.4426950e12f            // NEG_BIG * SCALE * log2(e)

// Scratch (static device globals: allocation-free per harness rules)
__device__ __align__(16) __half g_PcH[NG * LCC * LQQ];  // row softmax * mask [c][q]
__device__ __align__(16) __half g_PqH[NG * LCC * LQQ];  // col softmax * mask [c][q]

// ---------------------------------------------------------------------------
// helpers
// ---------------------------------------------------------------------------
static __device__ __forceinline__ uint32_t smem_u32(const void* p) {
    uint32_t a;
    asm("{ .reg .u64 t; cvta.to.shared.u64 t, %1; cvt.u32.u64 %0, t; }"
        : "=r"(a) : "l"(p));
    return a;
}

static __device__ __forceinline__ uint32_t pack_bf2(float lo, float hi) {
    uint32_t r;
    asm("cvt.rn.bf16x2.f32 %0, %1, %2;" : "=r"(r) : "f"(hi), "f"(lo));
    return r;
}

// split a float4 into bf16 hi/lo pairs and store 8B each to smem (fused_S)
static __device__ __forceinline__ void split_store(uint8_t* sh, uint8_t* sl,
                                                   int off, float4 v) {
    float hx = __bfloat162float(__float2bfloat16(v.x));
    float hy = __bfloat162float(__float2bfloat16(v.y));
    float hz = __bfloat162float(__float2bfloat16(v.z));
    float hw = __bfloat162float(__float2bfloat16(v.w));
    uint2 H, L;
    H.x = pack_bf2(hx, hy);
    H.y = pack_bf2(hz, hw);
    L.x = pack_bf2(v.x - hx, v.y - hy);
    L.y = pack_bf2(v.z - hz, v.w - hw);
    *(uint2*)(sh + off) = H;
    *(uint2*)(sl + off) = L;
}

// split a float4 into fp16 hi/lo pairs and store 8B each to smem (nn_gemm B)
static __device__ __forceinline__ void split_store_h(uint8_t* sh, uint8_t* sl,
                                                     int off, float4 v) {
    __half hx = __float2half_rn(v.x), hy = __float2half_rn(v.y);
    __half hz = __float2half_rn(v.z), hw = __float2half_rn(v.w);
    __half2 H0 = __halves2half2(hx, hy), H1 = __halves2half2(hz, hw);
    __half2 L0 = __floats2half2_rn(v.x - __half2float(hx), v.y - __half2float(hy));
    __half2 L1 = __floats2half2_rn(v.z - __half2float(hz), v.w - __half2float(hw));
    uint2 H, L;
    H.x = *(uint32_t*)&H0; H.y = *(uint32_t*)&H1;
    L.x = *(uint32_t*)&L0; L.y = *(uint32_t*)&L1;
    *(uint2*)(sh + off) = H;
    *(uint2*)(sl + off) = L;
}

static __device__ __forceinline__ void ldm4(uint32_t* r, uint32_t a) {
    asm volatile("ldmatrix.sync.aligned.m8n8.x4.shared.b16 {%0,%1,%2,%3}, [%4];"
                 : "=r"(r[0]), "=r"(r[1]), "=r"(r[2]), "=r"(r[3]) : "r"(a));
}
static __device__ __forceinline__ void ldm4t(uint32_t* r, uint32_t a) {
    asm volatile("ldmatrix.sync.aligned.m8n8.x4.trans.shared.b16 {%0,%1,%2,%3}, [%4];"
                 : "=r"(r[0]), "=r"(r[1]), "=r"(r[2]), "=r"(r[3]) : "r"(a));
}

static __device__ __forceinline__ void mma16816(float* d, const uint32_t* a,
                                                const uint32_t* b) {
    asm volatile(
        "mma.sync.aligned.m16n8k16.row.col.f32.bf16.bf16.f32 "
        "{%0,%1,%2,%3}, {%4,%5,%6,%7}, {%8,%9}, {%0,%1,%2,%3};"
        : "+f"(d[0]), "+f"(d[1]), "+f"(d[2]), "+f"(d[3])
        : "r"(a[0]), "r"(a[1]), "r"(a[2]), "r"(a[3]), "r"(b[0]), "r"(b[1]));
}
static __device__ __forceinline__ void mma16816h(float* d, const uint32_t* a,
                                                 const uint32_t* b) {
    asm volatile(
        "mma.sync.aligned.m16n8k16.row.col.f32.f16.f16.f32 "
        "{%0,%1,%2,%3}, {%4,%5,%6,%7}, {%8,%9}, {%0,%1,%2,%3};"
        : "+f"(d[0]), "+f"(d[1]), "+f"(d[2]), "+f"(d[3])
        : "r"(a[0]), "r"(a[1]), "r"(a[2]), "r"(a[3]), "r"(b[0]), "r"(b[1]));
}

// ---------------------------------------------------------------------------
// Fused: S logits (log2 domain) via HMMA bf16 hi/lo, kept ENTIRELY in the
// accumulator registers. Dual softmax via shfl + tiny smem partials.
// P_q / P_c leave through a padded fp16 smem buffer (EC, reuses dead staging)
// so all global P writes are 16B coalesced. One CTA/group, 512 thr, 16 warps.
// ---------------------------------------------------------------------------
#define OFF_AH     0
#define OFF_AL     20480
#define OFF_BH     40960
#define OFF_BL     51200                    // staging ends 61440
#define ECSTRIDE   272                      // bytes per 128-col fp16 row
#define OFF_EC     0                        // reuses staging after k-loop
#define OFF_CMS    69632                    // 256 f  (EC = 256*272 = 69632)
#define OFF_QMS    (OFF_CMS + 1024)         // 128 f
#define OFF_IC     (OFF_QMS + 512)          // 256 f
#define OFF_IQ     (OFF_IC + 1024)          // 128 f
#define OFF_RMAX   (OFF_IQ + 512)           // 256 f
#define OFF_RINV   (OFF_RMAX + 1024)        // 256 f
#define OFF_CMAX   (OFF_RINV + 1024)        // 128 f
#define OFF_CINV   (OFF_CMAX + 512)         // 128 f
#define OFF_RPART  (OFF_CINV + 512)         // 4*256 f
#define OFF_CPART  (OFF_RPART + 4096)       // 4*128 f
#define SMEM_FUSED (OFF_CPART + 2048)       // 81920 bytes

__global__ __launch_bounds__(512, 1) void fused_S(
    const float* __restrict__ Cin, const float* __restrict__ Qin,
    const float* __restrict__ cm, const float* __restrict__ qm,
    float* __restrict__ outM, float* __restrict__ outMT) {
    extern __shared__ __align__(16) uint8_t dsm[];
    uint8_t* Ah   = dsm + OFF_AH;
    uint8_t* Al   = dsm + OFF_AL;
    uint8_t* Bh   = dsm + OFF_BH;
    uint8_t* Bl   = dsm + OFF_BL;
    uint8_t* ecb  = dsm + OFF_EC;
    float* s_cm   = (float*)(dsm + OFF_CMS);
    float* s_qm   = (float*)(dsm + OFF_QMS);
    float* s_ic   = (float*)(dsm + OFF_IC);
    float* s_iq   = (float*)(dsm + OFF_IQ);
    float* rowmax = (float*)(dsm + OFF_RMAX);
    float* rowinv = (float*)(dsm + OFF_RINV);
    float* colmax = (float*)(dsm + OFF_CMAX);
    float* colinv = (float*)(dsm + OFF_CINV);
    float* rpart  = (float*)(dsm + OFF_RPART);
    float* cpart  = (float*)(dsm + OFF_CPART);

    int t = threadIdx.x, lane = t & 31, wid = t >> 5;
    int wm = wid & 3, wn = wid >> 2;
    int g2 = lane >> 2, t4 = lane & 3;
    int g = blockIdx.x;
    if (t < 256) s_cm[t] = cm[g * LCC + t];
    else if (t < 384) s_qm[t - 256] = qm[g * LQQ + (t - 256)];
    const float* Ag = Cin + (size_t)g * LCC * HD;
    const float* Bg = Qin + (size_t)g * LQQ * HD;

    float4 pvA[4], pvB[2];
    float sqA[4] = {}, sqB[2] = {};
#pragma unroll
    for (int i = 0; i < 4; i++) {
        int idx = t + i * 512;
        pvA[i] = *(const float4*)(Ag + (size_t)(idx >> 3) * HD + (idx & 7) * 4);
    }
#pragma unroll
    for (int i = 0; i < 2; i++) {
        int idx = t + i * 512;
        pvB[i] = *(const float4*)(Bg + (size_t)(idx >> 3) * HD + (idx & 7) * 4);
    }
    __syncthreads();

    // ---- mask outputs (independent; fills LDG latency) ----
    {
        float* oM = outM + (size_t)g * LCC * LQQ;
#pragma unroll
        for (int i = 0; i < 16; i++) {
            int base = (i * 512 + t) * 4;
            int r = base >> 7, c = base & 127;
            float cv = s_cm[r];
            float4 o = {cv * s_qm[c], cv * s_qm[c + 1], cv * s_qm[c + 2], cv * s_qm[c + 3]};
            *(float4*)(oM + base) = o;
        }
        float* oT = outMT + (size_t)g * LCC * LQQ;
#pragma unroll
        for (int i = 0; i < 16; i++) {
            int base = (i * 512 + t) * 4;
            int r = base >> 8, c = base & 255;
            float qv = s_qm[r];
            float4 o = {qv * s_cm[c], qv * s_cm[c + 1], qv * s_cm[c + 2], qv * s_cm[c + 3]};
            *(float4*)(oT + base) = o;
        }
    }

    // ---- K loop: 16 chunks of BK=32, register-prefetch pipelined ----
    float acc[4][4][4] = {};
    for (int kc = 0; kc < 16; kc++) {
#pragma unroll
        for (int i = 0; i < 4; i++) {
            int idx = t + i * 512;
            float4 v = pvA[i];
            sqA[i] = fmaf(v.x, v.x, fmaf(v.y, v.y, fmaf(v.z, v.z, fmaf(v.w, v.w, sqA[i]))));
            split_store(Ah, Al, (idx >> 3) * 80 + (idx & 7) * 8, v);
        }
#pragma unroll
        for (int i = 0; i < 2; i++) {
            int idx = t + i * 512;
            float4 v = pvB[i];
            sqB[i] = fmaf(v.x, v.x, fmaf(v.y, v.y, fmaf(v.z, v.z, fmaf(v.w, v.w, sqB[i]))));
            split_store(Bh, Bl, (idx >> 3) * 80 + (idx & 7) * 8, v);
        }
        __syncthreads();
        if (kc < 15) {
            int k0 = (kc + 1) * 32;
#pragma unroll
            for (int i = 0; i < 4; i++) {
                int idx = t + i * 512;
                pvA[i] = *(const float4*)(Ag + (size_t)(idx >> 3) * HD + k0 + (idx & 7) * 4);
            }
#pragma unroll
            for (int i = 0; i < 2; i++) {
                int idx = t + i * 512;
                pvB[i] = *(const float4*)(Bg + (size_t)(idx >> 3) * HD + k0 + (idx & 7) * 4);
            }
        }
#pragma unroll
        for (int k16 = 0; k16 < 2; k16++) {
            uint32_t af[4][4], bh[4][2], bl[4][2];
            int colb = k16 * 32 + ((lane >> 4) & 1) * 16;
            int ra = wm * 64 + (lane & 15);
            int rb = wn * 32 + (lane & 15);
#pragma unroll
            for (int bg2 = 0; bg2 < 2; bg2++) {
                uint32_t r4[4];
                ldm4(r4, smem_u32(Bh + (rb + bg2 * 16) * 80 + colb));
                bh[bg2 * 2][0] = r4[0]; bh[bg2 * 2][1] = r4[2];
                bh[bg2 * 2 + 1][0] = r4[1]; bh[bg2 * 2 + 1][1] = r4[3];
                ldm4(r4, smem_u32(Bl + (rb + bg2 * 16) * 80 + colb));
                bl[bg2 * 2][0] = r4[0]; bl[bg2 * 2][1] = r4[2];
                bl[bg2 * 2 + 1][0] = r4[1]; bl[bg2 * 2 + 1][1] = r4[3];
            }
#pragma unroll
            for (int fm = 0; fm < 4; fm++)
                ldm4(af[fm], smem_u32(Ah + (ra + fm * 16) * 80 + colb));
#pragma unroll
            for (int fm = 0; fm < 4; fm++)
#pragma unroll
                for (int ni = 0; ni < 4; ni++) {
                    mma16816(acc[fm][ni], af[fm], bh[ni]);
                    mma16816(acc[fm][ni], af[fm], bl[ni]);
                }
#pragma unroll
            for (int fm = 0; fm < 4; fm++)
                ldm4(af[fm], smem_u32(Al + (ra + fm * 16) * 80 + colb));
#pragma unroll
            for (int fm = 0; fm < 4; fm++)
#pragma unroll
                for (int ni = 0; ni < 4; ni++)
                    mma16816(acc[fm][ni], af[fm], bh[ni]);
        }
        __syncthreads();
    }

    // ---- in-kernel norms (log2-domain scale folded into s_ic) ----
#pragma unroll
    for (int i = 0; i < 4; i++) {
        float s = sqA[i];
        s += __shfl_xor_sync(0xffffffffu, s, 4);
        s += __shfl_xor_sync(0xffffffffu, s, 2);
        s += __shfl_xor_sync(0xffffffffu, s, 1);
        if ((t & 7) == 0)
            s_ic[(t >> 3) + 64 * i] = (FSCALE * LOG2E) / fmaxf(sqrtf(s), 1e-12f);
    }
#pragma unroll
    for (int i = 0; i < 2; i++) {
        float s = sqB[i];
        s += __shfl_xor_sync(0xffffffffu, s, 4);
        s += __shfl_xor_sync(0xffffffffu, s, 2);
        s += __shfl_xor_sync(0xffffffffu, s, 1);
        if ((t & 7) == 0) s_iq[(t >> 3) + 64 * i] = 1.f / fmaxf(sqrtf(s), 1e-12f);
    }
    __syncthreads();

    // ---- logits in registers (log2 domain) ----
    float iq8[8], qm8[8];
#pragma unroll
    for (int ni = 0; ni < 4; ni++)
#pragma unroll
        for (int b = 0; b < 2; b++) {
            int c = wn * 32 + ni * 8 + t4 * 2 + b;
            iq8[ni * 2 + b] = s_iq[c];
            qm8[ni * 2 + b] = s_qm[c];
        }
    float ic2[4][2], cv2[4][2];
#pragma unroll
    for (int fm = 0; fm < 4; fm++)
#pragma unroll
        for (int half = 0; half < 2; half++) {
            int r = wm * 64 + fm * 16 + g2 + half * 8;
            ic2[fm][half] = s_ic[r];
            cv2[fm][half] = s_cm[r];
        }
#pragma unroll
    for (int fm = 0; fm < 4; fm++)
#pragma unroll
        for (int ni = 0; ni < 4; ni++)
#pragma unroll
            for (int k = 0; k < 4; k++) {
                int half = k >> 1, b = k & 1;
                acc[fm][ni][k] = acc[fm][ni][k] * ic2[fm][half] * iq8[ni * 2 + b]
                               - FPEN2 * (1.f - cv2[fm][half] * qm8[ni * 2 + b]);
            }

    // ---- pass 1: maxes via shfl + 4-way partials ----
#pragma unroll
    for (int fm = 0; fm < 4; fm++)
#pragma unroll
        for (int half = 0; half < 2; half++) {
            float m = -3.0e38f;
#pragma unroll
            for (int ni = 0; ni < 4; ni++) {
                m = fmaxf(m, acc[fm][ni][half * 2]);
                m = fmaxf(m, acc[fm][ni][half * 2 + 1]);
            }
            m = fmaxf(m, __shfl_xor_sync(0xffffffffu, m, 1));
            m = fmaxf(m, __shfl_xor_sync(0xffffffffu, m, 2));
            if (t4 == 0)
                rpart[wn * 256 + wm * 64 + fm * 16 + g2 + half * 8] = m;
        }
#pragma unroll
    for (int ni = 0; ni < 4; ni++)
#pragma unroll
        for (int b = 0; b < 2; b++) {
            float m = -3.0e38f;
#pragma unroll
            for (int fm = 0; fm < 4; fm++) {
                m = fmaxf(m, acc[fm][ni][b]);
                m = fmaxf(m, acc[fm][ni][2 + b]);
            }
            m = fmaxf(m, __shfl_xor_sync(0xffffffffu, m, 4));
            m = fmaxf(m, __shfl_xor_sync(0xffffffffu, m, 8));
            m = fmaxf(m, __shfl_xor_sync(0xffffffffu, m, 16));
            if (g2 == 0)
                cpart[wm * 128 + wn * 32 + ni * 8 + t4 * 2 + b] = m;
        }
    __syncthreads();
    if (t < 256)
        rowmax[t] = fmaxf(fmaxf(rpart[t], rpart[256 + t]),
                          fmaxf(rpart[512 + t], rpart[768 + t]));
    else if (t < 384) {
        int c = t - 256;
        colmax[c] = fmaxf(fmaxf(cpart[c], cpart[128 + c]),
                          fmaxf(cpart[256 + c], cpart[384 + c]));
    }
    __syncthreads();

    // ---- pass 2: exps (e_r -> acc, e_c -> EC fp16), both sums ----
    float rm2[4][2], cmx[8];
#pragma unroll
    for (int fm = 0; fm < 4; fm++)
#pragma unroll
        for (int half = 0; half < 2; half++)
            rm2[fm][half] = rowmax[wm * 64 + fm * 16 + g2 + half * 8];
#pragma unroll
    for (int j = 0; j < 8; j++)
        cmx[j] = colmax[wn * 32 + (j >> 1) * 8 + t4 * 2 + (j & 1)];
    float rs[4][2] = {}, cs[8] = {};
#pragma unroll
    for (int fm = 0; fm < 4; fm++)
#pragma unroll
        for (int half = 0; half < 2; half++) {
            int r = wm * 64 + fm * 16 + g2 + half * 8;
#pragma unroll
            for (int ni = 0; ni < 4; ni++) {
                float v0 = acc[fm][ni][half * 2], v1 = acc[fm][ni][half * 2 + 1];
                float er0 = exp2f(v0 - rm2[fm][half]);
                float er1 = exp2f(v1 - rm2[fm][half]);
                float ec0 = exp2f(v0 - cmx[ni * 2]);
                float ec1 = exp2f(v1 - cmx[ni * 2 + 1]);
                rs[fm][half] += er0 + er1;
                cs[ni * 2] += ec0;
                cs[ni * 2 + 1] += ec1;
                acc[fm][ni][half * 2] = er0;
                acc[fm][ni][half * 2 + 1] = er1;
                __half2 h = __floats2half2_rn(ec0, ec1);
                int c = wn * 32 + ni * 8 + t4 * 2;
                *(uint32_t*)(ecb + r * ECSTRIDE + c * 2) = *(uint32_t*)&h;
            }
        }
    // reduce sums
#pragma unroll
    for (int fm = 0; fm < 4; fm++)
#pragma unroll
        for (int half = 0; half < 2; half++) {
            float s = rs[fm][half];
            s += __shfl_xor_sync(0xffffffffu, s, 1);
            s += __shfl_xor_sync(0xffffffffu, s, 2);
            if (t4 == 0)
                rpart[wn * 256 + wm * 64 + fm * 16 + g2 + half * 8] = s;
        }
#pragma unroll
    for (int j = 0; j < 8; j++) {
        float s = cs[j];
        s += __shfl_xor_sync(0xffffffffu, s, 4);
        s += __shfl_xor_sync(0xffffffffu, s, 8);
        s += __shfl_xor_sync(0xffffffffu, s, 16);
        if (g2 == 0)
            cpart[wm * 128 + wn * 32 + (j >> 1) * 8 + t4 * 2 + (j & 1)] = s;
    }
    __syncthreads();
    if (t < 256)
        rowinv[t] = s_cm[t] / (rpart[t] + rpart[256 + t] + rpart[512 + t] + rpart[768 + t]);
    else if (t < 384) {
        int c = t - 256;
        colinv[c] = s_qm[c] / (cpart[c] + cpart[128 + c] + cpart[256 + c] + cpart[384 + c]);
    }
    __syncthreads();

    // ---- P_q: scale EC by colinv*cm, coalesced 16B writes ----
    __half* Pq = g_PqH + (size_t)g * LCC * LQQ;
    __half* Pc = g_PcH + (size_t)g * LCC * LQQ;
#pragma unroll
    for (int i = 0; i < 8; i++) {
        int linear = i * 512 + t;
        int r = linear >> 4, c8 = (linear & 15) * 8;
        uint4 u = *(uint4*)(ecb + r * ECSTRIDE + c8 * 2);
        float cv = s_cm[r];
        __half2* hp = (__half2*)&u;
        uint4 o;
        __half2* op = (__half2*)&o;
#pragma unroll
        for (int j = 0; j < 4; j++) {
            float2 f = __half22float2(hp[j]);
            f.x *= colinv[c8 + j * 2] * cv;
            f.y *= colinv[c8 + j * 2 + 1] * cv;
            op[j] = __floats2half2_rn(f.x, f.y);
        }
        *(uint4*)(Pq + (size_t)r * LQQ + c8) = o;
    }
    __syncthreads();

    // ---- P_c: scale e_r in registers -> EC, then coalesced copy out ----
    float ri2[4][2];
#pragma unroll
    for (int fm = 0; fm < 4; fm++)
#pragma unroll
        for (int half = 0; half < 2; half++)
            ri2[fm][half] = rowinv[wm * 64 + fm * 16 + g2 + half * 8];
#pragma unroll
    for (int fm = 0; fm < 4; fm++)
#pragma unroll
        for (int half = 0; half < 2; half++) {
            int r = wm * 64 + fm * 16 + g2 + half * 8;
            float ri = ri2[fm][half];
#pragma unroll
            for (int ni = 0; ni < 4; ni++) {
                int c = wn * 32 + ni * 8 + t4 * 2;
                __half2 h = __floats2half2_rn(
                    acc[fm][ni][half * 2]     * ri * qm8[ni * 2],
                    acc[fm][ni][half * 2 + 1] * ri * qm8[ni * 2 + 1]);
                *(uint32_t*)(ecb + r * ECSTRIDE + c * 2) = *(uint32_t*)&h;
            }
        }
    __syncthreads();
#pragma unroll
    for (int i = 0; i < 8; i++) {
        int linear = i * 512 + t;
        int r = linear >> 4, c8 = (linear & 15) * 8;
        uint4 u = *(uint4*)(ecb + r * ECSTRIDE + c8 * 2);
        *(uint4*)(Pc + (size_t)r * LQQ + c8) = u;
    }
}

// ---------------------------------------------------------------------------
// NN GEMM: out[M,512] = A[M,K] @ B[K,512] per group, fp16 2-MMA scheme.
// A = P (fp16, single plane).  B = Q/C (fp32 -> fp16 hi/lo split, 2 MMAs).
// SMEM double buffer, one __syncthreads per k-chunk. (unchanged from R9)
// ---------------------------------------------------------------------------
template<bool ATRANS>
__global__ __launch_bounds__(256) void nn_gemm(const float* __restrict__ Bg0,
                                               float* __restrict__ out,
                                               int M, int K) {
    constexpr int ASZ = ATRANS ? (32 * 272) : (128 * 80);  // one fp16 plane
    constexpr int SS  = ASZ + 2 * 8704;                    // A | Bh | Bl
    extern __shared__ __align__(16) uint8_t dsm2[];
    int t = threadIdx.x, lane = t & 31, wid = t >> 5;
    int wm = wid & 1, wn = wid >> 1;
    int g = blockIdx.z, m0 = blockIdx.y * 128, n0 = blockIdx.x * 128;
    const __half* AgH = (ATRANS ? g_PqH : g_PcH) + (size_t)g * LCC * LQQ;
    const float* Bg = Bg0 + (size_t)g * K * HD;
    float acc[4][4][4] = {};
    int KCH = K >> 5;

    uint4 pvA[2];
    float4 pvB[4];

#define LOADA(kc_) do {                                                        \
    if (!ATRANS) {                                                             \
        const __half* p = AgH + (size_t)(m0 + (t >> 1)) * K + (kc_) * 32 + (t & 1) * 16; \
        pvA[0] = *(const uint4*)p; pvA[1] = *(const uint4*)(p + 8);            \
    } else {                                                                   \
        const __half* p = AgH + (size_t)((kc_) * 32 + (t >> 3)) * M + (t & 7) * 16; \
        pvA[0] = *(const uint4*)p; pvA[1] = *(const uint4*)(p + 8);            \
    } } while (0)
#define STOREA(Ap_) do {                                                       \
    uint8_t* d_ = (Ap_) + (!ATRANS ? ((t >> 1) * 80 + (t & 1) * 32)            \
                                   : ((t >> 3) * 272 + (t & 7) * 32));         \
    *(uint4*)d_ = pvA[0]; *(uint4*)(d_ + 16) = pvA[1]; } while (0)
#define LOADB(kc_) do {                                                        \
    _Pragma("unroll") for (int i = 0; i < 4; i++) {                            \
        int idx = t + i * 256;                                                 \
        pvB[i] = *(const float4*)(Bg + (size_t)((kc_) * 32 + (idx >> 5)) * HD + n0 + (idx & 31) * 4); \
    } } while (0)
#define STOREB(Bh_, Bl_) do {                                                  \
    _Pragma("unroll") for (int i = 0; i < 4; i++) {                            \
        int idx = t + i * 256;                                                 \
        split_store_h((Bh_), (Bl_), (idx >> 5) * 272 + (idx & 31) * 8, pvB[i]);\
    } } while (0)

    LOADA(0); LOADB(0);
    {
        uint8_t* Ap = dsm2;
        STOREA(Ap); STOREB(Ap + ASZ, Ap + ASZ + 8704);
    }

    for (int kc = 0; kc < KCH; kc++) {
        __syncthreads();
        uint8_t* Ap = dsm2 + (kc & 1) * SS;
        uint8_t* Bh = Ap + ASZ;
        uint8_t* Bl = Bh + 8704;
        bool more = (kc + 1 < KCH);
        if (more) { LOADA(kc + 1); LOADB(kc + 1); }
#pragma unroll
        for (int k16 = 0; k16 < 2; k16++) {
            uint32_t af[4][4], bh[4][2], bl[4][2];
            if (!ATRANS) {
                int colb = k16 * 32 + ((lane >> 4) & 1) * 16;
                int ra = wm * 64 + (lane & 15);
#pragma unroll
                for (int fm = 0; fm < 4; fm++)
                    ldm4(af[fm], smem_u32(Ap + (ra + fm * 16) * 80 + colb));
            } else {
                int row = k16 * 16 + (lane & 7) + ((lane >> 4) & 1) * 8;
                int cb  = wm * 128 + ((lane >> 3) & 1) * 16;
#pragma unroll
                for (int fm = 0; fm < 4; fm++)
                    ldm4t(af[fm], smem_u32(Ap + row * 272 + cb + fm * 32));
            }
            {
                int rowb = k16 * 16 + (lane & 7) + ((lane >> 3) & 1) * 8;
                int cbb  = wn * 64 + ((lane >> 4) & 1) * 16;
#pragma unroll
                for (int bg = 0; bg < 2; bg++) {
                    uint32_t r4[4];
                    ldm4t(r4, smem_u32(Bh + rowb * 272 + cbb + bg * 32));
                    bh[bg * 2][0] = r4[0]; bh[bg * 2][1] = r4[1];
                    bh[bg * 2 + 1][0] = r4[2]; bh[bg * 2 + 1][1] = r4[3];
                    ldm4t(r4, smem_u32(Bl + rowb * 272 + cbb + bg * 32));
                    bl[bg * 2][0] = r4[0]; bl[bg * 2][1] = r4[1];
                    bl[bg * 2 + 1][0] = r4[2]; bl[bg * 2 + 1][1] = r4[3];
                }
            }
#pragma unroll
            for (int fm = 0; fm < 4; fm++)
#pragma unroll
                for (int ni = 0; ni < 4; ni++) {
                    mma16816h(acc[fm][ni], af[fm], bh[ni]);
                    mma16816h(acc[fm][ni], af[fm], bl[ni]);
                }
        }
        if (more) {
            uint8_t* nAp = dsm2 + ((kc + 1) & 1) * SS;
            STOREA(nAp); STOREB(nAp + ASZ, nAp + ASZ + 8704);
        }
    }
#undef LOADA
#undef STOREA
#undef LOADB
#undef STOREB

    int g2 = lane >> 2, t4 = lane & 3;
#pragma unroll
    for (int fm = 0; fm < 4; fm++)
#pragma unroll
        for (int half = 0; half < 2; half++) {
            int row = m0 + wm * 64 + fm * 16 + g2 + half * 8;
            float* dst = out + ((size_t)g * M + row) * HD + n0;
#pragma unroll
            for (int ni = 0; ni < 4; ni++) {
                int col = wn * 32 + ni * 8 + t4 * 2;
                float2 o = {acc[fm][ni][half * 2], acc[fm][ni][half * 2 + 1]};
                *(float2*)(dst + col) = o;
            }
        }
}

// ---------------------------------------------------------------------------
extern "C" void kernel_launch(void* const* d_in, const int* in_sizes, int n_in,
                              void* d_out, int out_size) {
    const float* Cin = (const float*)d_in[0];
    const float* Qin = (const float*)d_in[1];
    const float* cm  = (const float*)d_in[2];
    const float* qm  = (const float*)d_in[3];
    float* out   = (float*)d_out;
    float* outAc = out;
    float* outAq = outAc + (size_t)NG * LCC * HD;
    float* outM  = outAq + (size_t)NG * LQQ * HD;
    float* outMT = outM  + (size_t)NG * LCC * LQQ;

    constexpr int SS_F = 128 * 80 + 2 * 8704;   // 27648
    constexpr int SS_T = 32 * 272 + 2 * 8704;   // 26112

    cudaFuncSetAttribute(fused_S, cudaFuncAttributeMaxDynamicSharedMemorySize,
                         SMEM_FUSED);
    cudaFuncSetAttribute(nn_gemm<false>,
                         cudaFuncAttributeMaxDynamicSharedMemorySize, 2 * SS_F);
    cudaFuncSetAttribute(nn_gemm<true>,
                         cudaFuncAttributeMaxDynamicSharedMemorySize, 2 * SS_T);

    fused_S<<<NG, 512, SMEM_FUSED>>>(Cin, Qin, cm, qm, outM, outMT);
    nn_gemm<false><<<dim3(4, 2, NG), 256, 2 * SS_F>>>(Qin, outAc, LCC, LQQ);
    nn_gemm<true ><<<dim3(4, 1, NG), 256, 2 * SS_T>>>(Cin, outAq, LQQ, LCC);
}

// round 13
// speedup vs baseline: 1.1754x; 1.0007x over previous
#include <cuda_runtime.h>
#include <cuda_bf16.h>
#include <cuda_fp16.h>
#include <stdint.h>
#include <math.h>

// Problem constants: B=16, X=4, I=8 -> G=512 groups; Lc=256, Lq=128, H=512
#define NG 512
#define LCC 256
#define LQQ 128
#define HD 512
#define FSCALE 100.0f
#define LOG2E 1.4426950408889634f
#define FPEN2 1.4426950e12f            // NEG_BIG * SCALE * log2(e)

// Scratch (static device globals: allocation-free per harness rules)
__device__ __align__(16) __half g_PcH[NG * LCC * LQQ];  // row softmax * mask [c][q]
__device__ __align__(16) __half g_PqH[NG * LCC * LQQ];  // col softmax * mask [c][q]

// ---------------------------------------------------------------------------
// helpers
// ---------------------------------------------------------------------------
static __device__ __forceinline__ uint32_t smem_u32(const void* p) {
    uint32_t a;
    asm("{ .reg .u64 t; cvta.to.shared.u64 t, %1; cvt.u32.u64 %0, t; }"
        : "=r"(a) : "l"(p));
    return a;
}

static __device__ __forceinline__ uint32_t pack_bf2(float lo, float hi) {
    uint32_t r;
    asm("cvt.rn.bf16x2.f32 %0, %1, %2;" : "=r"(r) : "f"(hi), "f"(lo));
    return r;
}

// split a float4 into bf16 hi/lo pairs and store 8B each to smem (fused_S)
static __device__ __forceinline__ void split_store(uint8_t* sh, uint8_t* sl,
                                                   int off, float4 v) {
    float hx = __bfloat162float(__float2bfloat16(v.x));
    float hy = __bfloat162float(__float2bfloat16(v.y));
    float hz = __bfloat162float(__float2bfloat16(v.z));
    float hw = __bfloat162float(__float2bfloat16(v.w));
    uint2 H, L;
    H.x = pack_bf2(hx, hy);
    H.y = pack_bf2(hz, hw);
    L.x = pack_bf2(v.x - hx, v.y - hy);
    L.y = pack_bf2(v.z - hz, v.w - hw);
    *(uint2*)(sh + off) = H;
    *(uint2*)(sl + off) = L;
}

// split a float4 into fp16 hi/lo pairs and store 8B each to smem (nn_gemm B)
static __device__ __forceinline__ void split_store_h(uint8_t* sh, uint8_t* sl,
                                                     int off, float4 v) {
    __half hx = __float2half_rn(v.x), hy = __float2half_rn(v.y);
    __half hz = __float2half_rn(v.z), hw = __float2half_rn(v.w);
    __half2 H0 = __halves2half2(hx, hy), H1 = __halves2half2(hz, hw);
    __half2 L0 = __floats2half2_rn(v.x - __half2float(hx), v.y - __half2float(hy));
    __half2 L1 = __floats2half2_rn(v.z - __half2float(hz), v.w - __half2float(hw));
    uint2 H, L;
    H.x = *(uint32_t*)&H0; H.y = *(uint32_t*)&H1;
    L.x = *(uint32_t*)&L0; L.y = *(uint32_t*)&L1;
    *(uint2*)(sh + off) = H;
    *(uint2*)(sl + off) = L;
}

static __device__ __forceinline__ void ldm4(uint32_t* r, uint32_t a) {
    asm volatile("ldmatrix.sync.aligned.m8n8.x4.shared.b16 {%0,%1,%2,%3}, [%4];"
                 : "=r"(r[0]), "=r"(r[1]), "=r"(r[2]), "=r"(r[3]) : "r"(a));
}
static __device__ __forceinline__ void ldm4t(uint32_t* r, uint32_t a) {
    asm volatile("ldmatrix.sync.aligned.m8n8.x4.trans.shared.b16 {%0,%1,%2,%3}, [%4];"
                 : "=r"(r[0]), "=r"(r[1]), "=r"(r[2]), "=r"(r[3]) : "r"(a));
}

static __device__ __forceinline__ void mma16816(float* d, const uint32_t* a,
                                                const uint32_t* b) {
    asm volatile(
        "mma.sync.aligned.m16n8k16.row.col.f32.bf16.bf16.f32 "
        "{%0,%1,%2,%3}, {%4,%5,%6,%7}, {%8,%9}, {%0,%1,%2,%3};"
        : "+f"(d[0]), "+f"(d[1]), "+f"(d[2]), "+f"(d[3])
        : "r"(a[0]), "r"(a[1]), "r"(a[2]), "r"(a[3]), "r"(b[0]), "r"(b[1]));
}
static __device__ __forceinline__ void mma16816h(float* d, const uint32_t* a,
                                                 const uint32_t* b) {
    asm volatile(
        "mma.sync.aligned.m16n8k16.row.col.f32.f16.f16.f32 "
        "{%0,%1,%2,%3}, {%4,%5,%6,%7}, {%8,%9}, {%0,%1,%2,%3};"
        : "+f"(d[0]), "+f"(d[1]), "+f"(d[2]), "+f"(d[3])
        : "r"(a[0]), "r"(a[1]), "r"(a[2]), "r"(a[3]), "r"(b[0]), "r"(b[1]));
}

// ---------------------------------------------------------------------------
// Fused: S logits (log2 domain) via HMMA bf16 hi/lo, kept ENTIRELY in the
// accumulator registers. Dual softmax via shfl + tiny smem partials.
// P_q / P_c leave through a padded fp16 smem buffer (EC, reuses dead staging)
// so all global P writes are 16B coalesced. One CTA/group, 512 thr, 16 warps.
// ---------------------------------------------------------------------------
#define OFF_AH     0
#define OFF_AL     20480
#define OFF_BH     40960
#define OFF_BL     51200                    // staging ends 61440
#define ECSTRIDE   272                      // bytes per 128-col fp16 row
#define OFF_EC     0                        // reuses staging after k-loop
#define OFF_CMS    69632                    // 256 f  (EC = 256*272 = 69632)
#define OFF_QMS    (OFF_CMS + 1024)         // 128 f
#define OFF_IC     (OFF_QMS + 512)          // 256 f
#define OFF_IQ     (OFF_IC + 1024)          // 128 f
#define OFF_RMAX   (OFF_IQ + 512)           // 256 f
#define OFF_RINV   (OFF_RMAX + 1024)        // 256 f
#define OFF_CMAX   (OFF_RINV + 1024)        // 128 f
#define OFF_CINV   (OFF_CMAX + 512)         // 128 f
#define OFF_RPART  (OFF_CINV + 512)         // 4*256 f
#define OFF_CPART  (OFF_RPART + 4096)       // 4*128 f
#define SMEM_FUSED (OFF_CPART + 2048)       // 81920 bytes

__global__ __launch_bounds__(512, 1) void fused_S(
    const float* __restrict__ Cin, const float* __restrict__ Qin,
    const float* __restrict__ cm, const float* __restrict__ qm,
    float* __restrict__ outM, float* __restrict__ outMT) {
    extern __shared__ __align__(16) uint8_t dsm[];
    uint8_t* Ah   = dsm + OFF_AH;
    uint8_t* Al   = dsm + OFF_AL;
    uint8_t* Bh   = dsm + OFF_BH;
    uint8_t* Bl   = dsm + OFF_BL;
    uint8_t* ecb  = dsm + OFF_EC;
    float* s_cm   = (float*)(dsm + OFF_CMS);
    float* s_qm   = (float*)(dsm + OFF_QMS);
    float* s_ic   = (float*)(dsm + OFF_IC);
    float* s_iq   = (float*)(dsm + OFF_IQ);
    float* rowmax = (float*)(dsm + OFF_RMAX);
    float* rowinv = (float*)(dsm + OFF_RINV);
    float* colmax = (float*)(dsm + OFF_CMAX);
    float* colinv = (float*)(dsm + OFF_CINV);
    float* rpart  = (float*)(dsm + OFF_RPART);
    float* cpart  = (float*)(dsm + OFF_CPART);

    int t = threadIdx.x, lane = t & 31, wid = t >> 5;
    int wm = wid & 3, wn = wid >> 2;
    int g2 = lane >> 2, t4 = lane & 3;
    int g = blockIdx.x;
    if (t < 256) s_cm[t] = cm[g * LCC + t];
    else if (t < 384) s_qm[t - 256] = qm[g * LQQ + (t - 256)];
    const float* Ag = Cin + (size_t)g * LCC * HD;
    const float* Bg = Qin + (size_t)g * LQQ * HD;

    float4 pvA[4], pvB[2];
    float sqA[4] = {}, sqB[2] = {};
#pragma unroll
    for (int i = 0; i < 4; i++) {
        int idx = t + i * 512;
        pvA[i] = *(const float4*)(Ag + (size_t)(idx >> 3) * HD + (idx & 7) * 4);
    }
#pragma unroll
    for (int i = 0; i < 2; i++) {
        int idx = t + i * 512;
        pvB[i] = *(const float4*)(Bg + (size_t)(idx >> 3) * HD + (idx & 7) * 4);
    }
    __syncthreads();

    // ---- mask outputs (independent; fills LDG latency) ----
    {
        float* oM = outM + (size_t)g * LCC * LQQ;
#pragma unroll
        for (int i = 0; i < 16; i++) {
            int base = (i * 512 + t) * 4;
            int r = base >> 7, c = base & 127;
            float cv = s_cm[r];
            float4 o = {cv * s_qm[c], cv * s_qm[c + 1], cv * s_qm[c + 2], cv * s_qm[c + 3]};
            *(float4*)(oM + base) = o;
        }
        float* oT = outMT + (size_t)g * LCC * LQQ;
#pragma unroll
        for (int i = 0; i < 16; i++) {
            int base = (i * 512 + t) * 4;
            int r = base >> 8, c = base & 255;
            float qv = s_qm[r];
            float4 o = {qv * s_cm[c], qv * s_cm[c + 1], qv * s_cm[c + 2], qv * s_cm[c + 3]};
            *(float4*)(oT + base) = o;
        }
    }

    // ---- K loop: 16 chunks of BK=32, register-prefetch pipelined ----
    float acc[4][4][4] = {};
    for (int kc = 0; kc < 16; kc++) {
#pragma unroll
        for (int i = 0; i < 4; i++) {
            int idx = t + i * 512;
            float4 v = pvA[i];
            sqA[i] = fmaf(v.x, v.x, fmaf(v.y, v.y, fmaf(v.z, v.z, fmaf(v.w, v.w, sqA[i]))));
            split_store(Ah, Al, (idx >> 3) * 80 + (idx & 7) * 8, v);
        }
#pragma unroll
        for (int i = 0; i < 2; i++) {
            int idx = t + i * 512;
            float4 v = pvB[i];
            sqB[i] = fmaf(v.x, v.x, fmaf(v.y, v.y, fmaf(v.z, v.z, fmaf(v.w, v.w, sqB[i]))));
            split_store(Bh, Bl, (idx >> 3) * 80 + (idx & 7) * 8, v);
        }
        __syncthreads();
        if (kc < 15) {
            int k0 = (kc + 1) * 32;
#pragma unroll
            for (int i = 0; i < 4; i++) {
                int idx = t + i * 512;
                pvA[i] = *(const float4*)(Ag + (size_t)(idx >> 3) * HD + k0 + (idx & 7) * 4);
            }
#pragma unroll
            for (int i = 0; i < 2; i++) {
                int idx = t + i * 512;
                pvB[i] = *(const float4*)(Bg + (size_t)(idx >> 3) * HD + k0 + (idx & 7) * 4);
            }
        }
#pragma unroll
        for (int k16 = 0; k16 < 2; k16++) {
            uint32_t af[4][4], bh[4][2], bl[4][2];
            int colb = k16 * 32 + ((lane >> 4) & 1) * 16;
            int ra = wm * 64 + (lane & 15);
            int rb = wn * 32 + (lane & 15);
#pragma unroll
            for (int bg2 = 0; bg2 < 2; bg2++) {
                uint32_t r4[4];
                ldm4(r4, smem_u32(Bh + (rb + bg2 * 16) * 80 + colb));
                bh[bg2 * 2][0] = r4[0]; bh[bg2 * 2][1] = r4[2];
                bh[bg2 * 2 + 1][0] = r4[1]; bh[bg2 * 2 + 1][1] = r4[3];
                ldm4(r4, smem_u32(Bl + (rb + bg2 * 16) * 80 + colb));
                bl[bg2 * 2][0] = r4[0]; bl[bg2 * 2][1] = r4[2];
                bl[bg2 * 2 + 1][0] = r4[1]; bl[bg2 * 2 + 1][1] = r4[3];
            }
#pragma unroll
            for (int fm = 0; fm < 4; fm++)
                ldm4(af[fm], smem_u32(Ah + (ra + fm * 16) * 80 + colb));
#pragma unroll
            for (int fm = 0; fm < 4; fm++)
#pragma unroll
                for (int ni = 0; ni < 4; ni++) {
                    mma16816(acc[fm][ni], af[fm], bh[ni]);
                    mma16816(acc[fm][ni], af[fm], bl[ni]);
                }
#pragma unroll
            for (int fm = 0; fm < 4; fm++)
                ldm4(af[fm], smem_u32(Al + (ra + fm * 16) * 80 + colb));
#pragma unroll
            for (int fm = 0; fm < 4; fm++)
#pragma unroll
                for (int ni = 0; ni < 4; ni++)
                    mma16816(acc[fm][ni], af[fm], bh[ni]);
        }
        __syncthreads();
    }

    // ---- in-kernel norms (log2-domain scale folded into s_ic) ----
#pragma unroll
    for (int i = 0; i < 4; i++) {
        float s = sqA[i];
        s += __shfl_xor_sync(0xffffffffu, s, 4);
        s += __shfl_xor_sync(0xffffffffu, s, 2);
        s += __shfl_xor_sync(0xffffffffu, s, 1);
        if ((t & 7) == 0)
            s_ic[(t >> 3) + 64 * i] = (FSCALE * LOG2E) / fmaxf(sqrtf(s), 1e-12f);
    }
#pragma unroll
    for (int i = 0; i < 2; i++) {
        float s = sqB[i];
        s += __shfl_xor_sync(0xffffffffu, s, 4);
        s += __shfl_xor_sync(0xffffffffu, s, 2);
        s += __shfl_xor_sync(0xffffffffu, s, 1);
        if ((t & 7) == 0) s_iq[(t >> 3) + 64 * i] = 1.f / fmaxf(sqrtf(s), 1e-12f);
    }
    __syncthreads();

    // ---- logits in registers (log2 domain) ----
    float iq8[8], qm8[8];
#pragma unroll
    for (int ni = 0; ni < 4; ni++)
#pragma unroll
        for (int b = 0; b < 2; b++) {
            int c = wn * 32 + ni * 8 + t4 * 2 + b;
            iq8[ni * 2 + b] = s_iq[c];
            qm8[ni * 2 + b] = s_qm[c];
        }
    float ic2[4][2], cv2[4][2];
#pragma unroll
    for (int fm = 0; fm < 4; fm++)
#pragma unroll
        for (int half = 0; half < 2; half++) {
            int r = wm * 64 + fm * 16 + g2 + half * 8;
            ic2[fm][half] = s_ic[r];
            cv2[fm][half] = s_cm[r];
        }
#pragma unroll
    for (int fm = 0; fm < 4; fm++)
#pragma unroll
        for (int ni = 0; ni < 4; ni++)
#pragma unroll
            for (int k = 0; k < 4; k++) {
                int half = k >> 1, b = k & 1;
                acc[fm][ni][k] = acc[fm][ni][k] * ic2[fm][half] * iq8[ni * 2 + b]
                               - FPEN2 * (1.f - cv2[fm][half] * qm8[ni * 2 + b]);
            }

    // ---- pass 1: maxes via shfl + 4-way partials ----
#pragma unroll
    for (int fm = 0; fm < 4; fm++)
#pragma unroll
        for (int half = 0; half < 2; half++) {
            float m = -3.0e38f;
#pragma unroll
            for (int ni = 0; ni < 4; ni++) {
                m = fmaxf(m, acc[fm][ni][half * 2]);
                m = fmaxf(m, acc[fm][ni][half * 2 + 1]);
            }
            m = fmaxf(m, __shfl_xor_sync(0xffffffffu, m, 1));
            m = fmaxf(m, __shfl_xor_sync(0xffffffffu, m, 2));
            if (t4 == 0)
                rpart[wn * 256 + wm * 64 + fm * 16 + g2 + half * 8] = m;
        }
#pragma unroll
    for (int ni = 0; ni < 4; ni++)
#pragma unroll
        for (int b = 0; b < 2; b++) {
            float m = -3.0e38f;
#pragma unroll
            for (int fm = 0; fm < 4; fm++) {
                m = fmaxf(m, acc[fm][ni][b]);
                m = fmaxf(m, acc[fm][ni][2 + b]);
            }
            m = fmaxf(m, __shfl_xor_sync(0xffffffffu, m, 4));
            m = fmaxf(m, __shfl_xor_sync(0xffffffffu, m, 8));
            m = fmaxf(m, __shfl_xor_sync(0xffffffffu, m, 16));
            if (g2 == 0)
                cpart[wm * 128 + wn * 32 + ni * 8 + t4 * 2 + b] = m;
        }
    __syncthreads();
    if (t < 256)
        rowmax[t] = fmaxf(fmaxf(rpart[t], rpart[256 + t]),
                          fmaxf(rpart[512 + t], rpart[768 + t]));
    else if (t < 384) {
        int c = t - 256;
        colmax[c] = fmaxf(fmaxf(cpart[c], cpart[128 + c]),
                          fmaxf(cpart[256 + c], cpart[384 + c]));
    }
    __syncthreads();

    // ---- pass 2: exps (e_r -> acc, e_c -> EC fp16), both sums ----
    float rm2[4][2], cmx[8];
#pragma unroll
    for (int fm = 0; fm < 4; fm++)
#pragma unroll
        for (int half = 0; half < 2; half++)
            rm2[fm][half] = rowmax[wm * 64 + fm * 16 + g2 + half * 8];
#pragma unroll
    for (int j = 0; j < 8; j++)
        cmx[j] = colmax[wn * 32 + (j >> 1) * 8 + t4 * 2 + (j & 1)];
    float rs[4][2] = {}, cs[8] = {};
#pragma unroll
    for (int fm = 0; fm < 4; fm++)
#pragma unroll
        for (int half = 0; half < 2; half++) {
            int r = wm * 64 + fm * 16 + g2 + half * 8;
#pragma unroll
            for (int ni = 0; ni < 4; ni++) {
                float v0 = acc[fm][ni][half * 2], v1 = acc[fm][ni][half * 2 + 1];
                float er0 = exp2f(v0 - rm2[fm][half]);
                float er1 = exp2f(v1 - rm2[fm][half]);
                float ec0 = exp2f(v0 - cmx[ni * 2]);
                float ec1 = exp2f(v1 - cmx[ni * 2 + 1]);
                rs[fm][half] += er0 + er1;
                cs[ni * 2] += ec0;
                cs[ni * 2 + 1] += ec1;
                acc[fm][ni][half * 2] = er0;
                acc[fm][ni][half * 2 + 1] = er1;
                __half2 h = __floats2half2_rn(ec0, ec1);
                int c = wn * 32 + ni * 8 + t4 * 2;
                *(uint32_t*)(ecb + r * ECSTRIDE + c * 2) = *(uint32_t*)&h;
            }
        }
    // reduce sums
#pragma unroll
    for (int fm = 0; fm < 4; fm++)
#pragma unroll
        for (int half = 0; half < 2; half++) {
            float s = rs[fm][half];
            s += __shfl_xor_sync(0xffffffffu, s, 1);
            s += __shfl_xor_sync(0xffffffffu, s, 2);
            if (t4 == 0)
                rpart[wn * 256 + wm * 64 + fm * 16 + g2 + half * 8] = s;
        }
#pragma unroll
    for (int j = 0; j < 8; j++) {
        float s = cs[j];
        s += __shfl_xor_sync(0xffffffffu, s, 4);
        s += __shfl_xor_sync(0xffffffffu, s, 8);
        s += __shfl_xor_sync(0xffffffffu, s, 16);
        if (g2 == 0)
            cpart[wm * 128 + wn * 32 + (j >> 1) * 8 + t4 * 2 + (j & 1)] = s;
    }
    __syncthreads();
    if (t < 256)
        rowinv[t] = s_cm[t] / (rpart[t] + rpart[256 + t] + rpart[512 + t] + rpart[768 + t]);
    else if (t < 384) {
        int c = t - 256;
        colinv[c] = s_qm[c] / (cpart[c] + cpart[128 + c] + cpart[256 + c] + cpart[384 + c]);
    }
    __syncthreads();

    // ---- P_q: scale EC by colinv*cm, coalesced 16B writes ----
    __half* Pq = g_PqH + (size_t)g * LCC * LQQ;
    __half* Pc = g_PcH + (size_t)g * LCC * LQQ;
#pragma unroll
    for (int i = 0; i < 8; i++) {
        int linear = i * 512 + t;
        int r = linear >> 4, c8 = (linear & 15) * 8;
        uint4 u = *(uint4*)(ecb + r * ECSTRIDE + c8 * 2);
        float cv = s_cm[r];
        __half2* hp = (__half2*)&u;
        uint4 o;
        __half2* op = (__half2*)&o;
#pragma unroll
        for (int j = 0; j < 4; j++) {
            float2 f = __half22float2(hp[j]);
            f.x *= colinv[c8 + j * 2] * cv;
            f.y *= colinv[c8 + j * 2 + 1] * cv;
            op[j] = __floats2half2_rn(f.x, f.y);
        }
        *(uint4*)(Pq + (size_t)r * LQQ + c8) = o;
    }
    __syncthreads();

    // ---- P_c: scale e_r in registers -> EC, then coalesced copy out ----
    float ri2[4][2];
#pragma unroll
    for (int fm = 0; fm < 4; fm++)
#pragma unroll
        for (int half = 0; half < 2; half++)
            ri2[fm][half] = rowinv[wm * 64 + fm * 16 + g2 + half * 8];
#pragma unroll
    for (int fm = 0; fm < 4; fm++)
#pragma unroll
        for (int half = 0; half < 2; half++) {
            int r = wm * 64 + fm * 16 + g2 + half * 8;
            float ri = ri2[fm][half];
#pragma unroll
            for (int ni = 0; ni < 4; ni++) {
                int c = wn * 32 + ni * 8 + t4 * 2;
                __half2 h = __floats2half2_rn(
                    acc[fm][ni][half * 2]     * ri * qm8[ni * 2],
                    acc[fm][ni][half * 2 + 1] * ri * qm8[ni * 2 + 1]);
                *(uint32_t*)(ecb + r * ECSTRIDE + c * 2) = *(uint32_t*)&h;
            }
        }
    __syncthreads();
#pragma unroll
    for (int i = 0; i < 8; i++) {
        int linear = i * 512 + t;
        int r = linear >> 4, c8 = (linear & 15) * 8;
        uint4 u = *(uint4*)(ecb + r * ECSTRIDE + c8 * 2);
        *(uint4*)(Pc + (size_t)r * LQQ + c8) = u;
    }
}

// ---------------------------------------------------------------------------
// NN GEMM: out[M,512] = A[M,K] @ B[K,512] per group, fp16 2-MMA scheme.
// A = P (fp16, single plane).  B = Q/C (fp32 -> fp16 hi/lo split, 2 MMAs).
// SMEM double buffer, one __syncthreads per k-chunk. (unchanged from R9)
// ---------------------------------------------------------------------------
template<bool ATRANS>
__global__ __launch_bounds__(256) void nn_gemm(const float* __restrict__ Bg0,
                                               float* __restrict__ out,
                                               int M, int K) {
    constexpr int ASZ = ATRANS ? (32 * 272) : (128 * 80);  // one fp16 plane
    constexpr int SS  = ASZ + 2 * 8704;                    // A | Bh | Bl
    extern __shared__ __align__(16) uint8_t dsm2[];
    int t = threadIdx.x, lane = t & 31, wid = t >> 5;
    int wm = wid & 1, wn = wid >> 1;
    int g = blockIdx.z, m0 = blockIdx.y * 128, n0 = blockIdx.x * 128;
    const __half* AgH = (ATRANS ? g_PqH : g_PcH) + (size_t)g * LCC * LQQ;
    const float* Bg = Bg0 + (size_t)g * K * HD;
    float acc[4][4][4] = {};
    int KCH = K >> 5;

    uint4 pvA[2];
    float4 pvB[4];

#define LOADA(kc_) do {                                                        \
    if (!ATRANS) {                                                             \
        const __half* p = AgH + (size_t)(m0 + (t >> 1)) * K + (kc_) * 32 + (t & 1) * 16; \
        pvA[0] = *(const uint4*)p; pvA[1] = *(const uint4*)(p + 8);            \
    } else {                                                                   \
        const __half* p = AgH + (size_t)((kc_) * 32 + (t >> 3)) * M + (t & 7) * 16; \
        pvA[0] = *(const uint4*)p; pvA[1] = *(const uint4*)(p + 8);            \
    } } while (0)
#define STOREA(Ap_) do {                                                       \
    uint8_t* d_ = (Ap_) + (!ATRANS ? ((t >> 1) * 80 + (t & 1) * 32)            \
                                   : ((t >> 3) * 272 + (t & 7) * 32));         \
    *(uint4*)d_ = pvA[0]; *(uint4*)(d_ + 16) = pvA[1]; } while (0)
#define LOADB(kc_) do {                                                        \
    _Pragma("unroll") for (int i = 0; i < 4; i++) {                            \
        int idx = t + i * 256;                                                 \
        pvB[i] = *(const float4*)(Bg + (size_t)((kc_) * 32 + (idx >> 5)) * HD + n0 + (idx & 31) * 4); \
    } } while (0)
#define STOREB(Bh_, Bl_) do {                                                  \
    _Pragma("unroll") for (int i = 0; i < 4; i++) {                            \
        int idx = t + i * 256;                                                 \
        split_store_h((Bh_), (Bl_), (idx >> 5) * 272 + (idx & 31) * 8, pvB[i]);\
    } } while (0)

    LOADA(0); LOADB(0);
    {
        uint8_t* Ap = dsm2;
        STOREA(Ap); STOREB(Ap + ASZ, Ap + ASZ + 8704);
    }

    for (int kc = 0; kc < KCH; kc++) {
        __syncthreads();
        uint8_t* Ap = dsm2 + (kc & 1) * SS;
        uint8_t* Bh = Ap + ASZ;
        uint8_t* Bl = Bh + 8704;
        bool more = (kc + 1 < KCH);
        if (more) { LOADA(kc + 1); LOADB(kc + 1); }
#pragma unroll
        for (int k16 = 0; k16 < 2; k16++) {
            uint32_t af[4][4], bh[4][2], bl[4][2];
            if (!ATRANS) {
                int colb = k16 * 32 + ((lane >> 4) & 1) * 16;
                int ra = wm * 64 + (lane & 15);
#pragma unroll
                for (int fm = 0; fm < 4; fm++)
                    ldm4(af[fm], smem_u32(Ap + (ra + fm * 16) * 80 + colb));
            } else {
                int row = k16 * 16 + (lane & 7) + ((lane >> 4) & 1) * 8;
                int cb  = wm * 128 + ((lane >> 3) & 1) * 16;
#pragma unroll
                for (int fm = 0; fm < 4; fm++)
                    ldm4t(af[fm], smem_u32(Ap + row * 272 + cb + fm * 32));
            }
            {
                int rowb = k16 * 16 + (lane & 7) + ((lane >> 3) & 1) * 8;
                int cbb  = wn * 64 + ((lane >> 4) & 1) * 16;
#pragma unroll
                for (int bg = 0; bg < 2; bg++) {
                    uint32_t r4[4];
                    ldm4t(r4, smem_u32(Bh + rowb * 272 + cbb + bg * 32));
                    bh[bg * 2][0] = r4[0]; bh[bg * 2][1] = r4[1];
                    bh[bg * 2 + 1][0] = r4[2]; bh[bg * 2 + 1][1] = r4[3];
                    ldm4t(r4, smem_u32(Bl + rowb * 272 + cbb + bg * 32));
                    bl[bg * 2][0] = r4[0]; bl[bg * 2][1] = r4[1];
                    bl[bg * 2 + 1][0] = r4[2]; bl[bg * 2 + 1][1] = r4[3];
                }
            }
#pragma unroll
            for (int fm = 0; fm < 4; fm++)
#pragma unroll
                for (int ni = 0; ni < 4; ni++) {
                    mma16816h(acc[fm][ni], af[fm], bh[ni]);
                    mma16816h(acc[fm][ni], af[fm], bl[ni]);
                }
        }
        if (more) {
            uint8_t* nAp = dsm2 + ((kc + 1) & 1) * SS;
            STOREA(nAp); STOREB(nAp + ASZ, nAp + ASZ + 8704);
        }
    }
#undef LOADA
#undef STOREA
#undef LOADB
#undef STOREB

    int g2 = lane >> 2, t4 = lane & 3;
#pragma unroll
    for (int fm = 0; fm < 4; fm++)
#pragma unroll
        for (int half = 0; half < 2; half++) {
            int row = m0 + wm * 64 + fm * 16 + g2 + half * 8;
            float* dst = out + ((size_t)g * M + row) * HD + n0;
#pragma unroll
            for (int ni = 0; ni < 4; ni++) {
                int col = wn * 32 + ni * 8 + t4 * 2;
                float2 o = {acc[fm][ni][half * 2], acc[fm][ni][half * 2 + 1]};
                *(float2*)(dst + col) = o;
            }
        }
}

// ---------------------------------------------------------------------------
extern "C" void kernel_launch(void* const* d_in, const int* in_sizes, int n_in,
                              void* d_out, int out_size) {
    const float* Cin = (const float*)d_in[0];
    const float* Qin = (const float*)d_in[1];
    const float* cm  = (const float*)d_in[2];
    const float* qm  = (const float*)d_in[3];
    float* out   = (float*)d_out;
    float* outAc = out;
    float* outAq = outAc + (size_t)NG * LCC * HD;
    float* outM  = outAq + (size_t)NG * LQQ * HD;
    float* outMT = outM  + (size_t)NG * LCC * LQQ;

    constexpr int SS_F = 128 * 80 + 2 * 8704;   // 27648
    constexpr int SS_T = 32 * 272 + 2 * 8704;   // 26112

    cudaFuncSetAttribute(fused_S, cudaFuncAttributeMaxDynamicSharedMemorySize,
                         SMEM_FUSED);
    cudaFuncSetAttribute(nn_gemm<false>,
                         cudaFuncAttributeMaxDynamicSharedMemorySize, 2 * SS_F);
    cudaFuncSetAttribute(nn_gemm<true>,
                         cudaFuncAttributeMaxDynamicSharedMemorySize, 2 * SS_T);

    fused_S<<<NG, 512, SMEM_FUSED>>>(Cin, Qin, cm, qm, outM, outMT);
    nn_gemm<false><<<dim3(4, 2, NG), 256, 2 * SS_F>>>(Qin, outAc, LCC, LQQ);
    nn_gemm<true ><<<dim3(4, 1, NG), 256, 2 * SS_T>>>(Cin, outAq, LQQ, LCC);
}